// round 5
// baseline (speedup 1.0000x reference)
#include <cuda_runtime.h>
#include <cstdint>
#include <math.h>

// ---------------- problem constants ----------------
#define S_TOK   1024
#define HID     768
#define NE      64
#define TK      8
#define CAPMAX  256
#define I1      3072
#define I2      6144

// ---------------- GEMM tiling ----------------
#define BM   256
#define BK   32
// fragment-order smem: A = 16 m_tiles x 4 ks x 32 lanes x 4 regs x 4B = 32768B
//                      B = 16 n_tiles x 4 ks x 32 lanes x 2 regs x 4B = 16384B
#define A_FRAG_BYTES 32768
#define B_FRAG_BYTES 16384
#define STG          (A_FRAG_BYTES + B_FRAG_BYTES)   // 49152
#define SMEM_BYTES   (2 * STG)                       // 98304
#define NC1 (HID / BK)   // 24
#define NC2 (I1 / BK)    // 96

// ---------------- device scratch ----------------
__device__ __align__(16)  float g_topw[S_TOK][TK];
__device__ __align__(16)  int   g_topi[S_TOK][TK];
__device__ __align__(16)  int   g_slot[S_TOK][TK];
__device__ __align__(16)  int   g_ecount[NE];
__device__ __align__(16)  int   g_etok[NE][CAPMAX];
__device__ __align__(256) float g_sh_gated[S_TOK][I1];
__device__ __align__(256) float g_ex_gated[NE][CAPMAX][I1];
__device__ __align__(256) float g_ex_out[NE][CAPMAX][HID];

// ---------------- helpers ----------------
__device__ __forceinline__ uint32_t smem_u32(const void* p) {
    uint32_t a;
    asm("{ .reg .u64 t; cvta.to.shared.u64 t, %1; cvt.u32.u64 %0, t; }" : "=r"(a) : "l"(p));
    return a;
}
__device__ __forceinline__ void lds128(uint32_t* r, uint32_t a) {
    asm volatile("ld.shared.v4.b32 {%0,%1,%2,%3}, [%4];"
                 : "=r"(r[0]), "=r"(r[1]), "=r"(r[2]), "=r"(r[3]) : "r"(a));
}
__device__ __forceinline__ void lds64(uint32_t* r, uint32_t a) {
    asm volatile("ld.shared.v2.b32 {%0,%1}, [%2];"
                 : "=r"(r[0]), "=r"(r[1]) : "r"(a));
}
__device__ __forceinline__ void sts_tf32(uint32_t addr, float f) {
    uint32_t v;
    asm volatile("cvt.rna.tf32.f32 %0, %1;" : "=r"(v) : "f"(f));
    asm volatile("st.shared.b32 [%0], %1;" :: "r"(addr), "r"(v) : "memory");
}
#define MMA_TF32(c, a, b0v, b1v) \
    asm volatile("mma.sync.aligned.m16n8k8.row.col.f32.tf32.tf32.f32 " \
        "{%0,%1,%2,%3}, {%4,%5,%6,%7}, {%8,%9}, {%0,%1,%2,%3};" \
        : "+f"((c)[0]), "+f"((c)[1]), "+f"((c)[2]), "+f"((c)[3]) \
        : "r"((a)[0]), "r"((a)[1]), "r"((a)[2]), "r"((a)[3]), "r"(b0v), "r"(b1v))

extern __shared__ char dsm[];

// ---------------- gating ----------------
__global__ void gating_kernel(const float* __restrict__ x,
                              const float* __restrict__ wg) {
    int s = blockIdx.x;
    __shared__ float xs[HID];
    __shared__ float logits_s[NE];
    int tid = threadIdx.x;

    for (int i = tid; i < HID; i += 256) xs[i] = x[(size_t)s * HID + i];
    __syncthreads();

    int e = tid >> 2, sub = tid & 3;
    const float* w = wg + (size_t)e * HID;
    float acc = 0.f;
    for (int i = sub; i < HID; i += 4) acc += xs[i] * w[i];
    acc += __shfl_down_sync(0xffffffffu, acc, 2);
    acc += __shfl_down_sync(0xffffffffu, acc, 1);
    if (sub == 0) logits_s[e] = acc;
    __syncthreads();

    if (tid < 32) {
        float v0 = logits_s[tid];
        float v1 = logits_s[tid + 32];
        float tv[TK]; int tix[TK];
#pragma unroll
        for (int r = 0; r < TK; r++) {
            float bv; int bi;
            if (v0 >= v1) { bv = v0; bi = tid; }
            else          { bv = v1; bi = tid + 32; }
#pragma unroll
            for (int off = 16; off > 0; off >>= 1) {
                float ov = __shfl_down_sync(0xffffffffu, bv, off);
                int   oi = __shfl_down_sync(0xffffffffu, bi, off);
                if (ov > bv || (ov == bv && oi < bi)) { bv = ov; bi = oi; }
            }
            bv = __shfl_sync(0xffffffffu, bv, 0);
            bi = __shfl_sync(0xffffffffu, bi, 0);
            if (bi == tid)      v0 = -INFINITY;
            if (bi == tid + 32) v1 = -INFINITY;
            tv[r] = bv; tix[r] = bi;
        }
        if (tid == 0) {
            float m = tv[0], wv[TK], D = 0.f;
#pragma unroll
            for (int r = 0; r < TK; r++) { wv[r] = expf(tv[r] - m); D += wv[r]; }
            D = fmaxf(D, 1.1920929e-7f);
#pragma unroll
            for (int r = 0; r < TK; r++) { g_topw[s][r] = wv[r] / D; g_topi[s][r] = tix[r]; }
        }
    }
}

// ---------------- priority ----------------
__global__ void priority_kernel(const int* __restrict__ capacity) {
    int e = blockIdx.x, lane = threadIdx.x;
    int cap = capacity[0];
    if (cap > CAPMAX) cap = CAPMAX;
    if (cap < 0) cap = 0;

    int offset = 0;
    for (int base = 0; base < S_TOK * TK; base += 32) {
        int p = base + lane;
        int k = p / S_TOK;
        int s = p - k * S_TOK;
        bool match = (g_topi[s][k] == e);
        unsigned mask = __ballot_sync(0xffffffffu, match);
        if (match) {
            int c = offset + __popc(mask & ((1u << lane) - 1u));
            if (c < cap) { g_slot[s][k] = c; g_etok[e][c] = s; }
            else         { g_slot[s][k] = -1; }
        }
        offset += __popc(mask);
    }
    if (lane == 0) g_ecount[e] = (offset < cap) ? offset : cap;
}

// Store one float4 (consecutive k) into fragment-order A region.
// Precomputed per-thread: base offset and 4 j-offsets.
__device__ __forceinline__ void sts_frag4(uint32_t base, const uint32_t* jo, float4 v) {
    sts_tf32(base + jo[0], v.x);
    sts_tf32(base + jo[1], v.y);
    sts_tf32(base + jo[2], v.z);
    sts_tf32(base + jo[3], v.w);
}

// ---------------- GEMM1 (tf32 mma.sync, frag-order smem) + SwiGLU ----------------
// Block: 256 rows x 64 cols (pair: g1 + g2). 16 warps 4(M)x4(N).
__global__ __launch_bounds__(512, 1)
void gemm1_mma(const float* __restrict__ X, const float* __restrict__ W, int shared_mode) {
    int e = blockIdx.z;
    int M; const int* gather; const float* Wp; float* Out;
    if (shared_mode) { M = S_TOK; gather = nullptr; Wp = W; Out = &g_sh_gated[0][0]; }
    else {
        M = g_ecount[e]; gather = g_etok[e];
        Wp = W + (size_t)e * I2 * HID; Out = &g_ex_gated[e][0][0];
    }
    int m0 = blockIdx.y * BM;
    if (m0 >= M) return;
    int n0 = blockIdx.x * 64;
    int Mrem = M - m0;
    int Mceil = (Mrem + 15) & ~15;

    uint32_t sb = smem_u32(dsm);
    int t = threadIdx.x, lane = t & 31, wid = t >> 5;
    int wm = wid >> 2, wn = wid & 3;     // 4 x 4 warp grid; warp = 64 rows x 16 cols
    int lq = lane >> 2, lr = lane & 3;

    // per-warp row limit (skip dead mt tiles)
    int wrem = Mrem - wm * 64;
    int mt_lim = (wrem >= 64) ? 4 : ((wrem <= 0) ? 0 : ((wrem + 15) >> 4));

    // ---- loader constants ----
    int kseg = t & 7;          // float4 column group
    int r64  = t >> 3;         // 0..63 row within pass
    int ksw  = kseg >> 1;      // ks of this thread's data
    int gID  = r64 & 7;
    int regA = ((r64 >> 3) & 1) + 2 * (kseg & 1);
    int swzA = ksw ^ ((gID >> 1) & 1);

    uint32_t aoff[4], ajo[4], bjo[4];
#pragma unroll
    for (int p = 0; p < 4; p++)
        aoff[p] = (uint32_t)((p * 4 + (r64 >> 4)) * 2048 + ksw * 512 + gID * 64 + regA * 4);
#pragma unroll
    for (int j = 0; j < 4; j++) { ajo[j] = (uint32_t)((j ^ swzA) << 4); bjo[j] = (uint32_t)((j ^ ksw) << 3); }
    uint32_t boff[2];
#pragma unroll
    for (int p = 0; p < 2; p++)
        boff[p] = (uint32_t)(A_FRAG_BYTES + (p * 8 + (r64 >> 3)) * 1024 + ksw * 256 + gID * 32 + (kseg & 1) * 4);

    // pass enables / global pointers
    bool doA[4];
    const float* ap[4];
#pragma unroll
    for (int p = 0; p < 4; p++) {
        doA[p] = (p * 64) < Mceil;
        int m = m0 + p * 64 + r64;
        ap[p] = (m < M) ? (X + (size_t)(gather ? gather[m] : m) * HID + kseg * 4) : nullptr;
    }
    const float* bp[2];
    bp[0] = Wp + (size_t)(n0 + r64) * HID + kseg * 4;
    bp[1] = Wp + (size_t)(I1 + n0 + r64) * HID + kseg * 4;

    float acc1[4][2][4], acc2[4][2][4];
#pragma unroll
    for (int mt = 0; mt < 4; mt++)
#pragma unroll
        for (int nt = 0; nt < 2; nt++)
#pragma unroll
            for (int i = 0; i < 4; i++) { acc1[mt][nt][i] = 0.f; acc2[mt][nt][i] = 0.f; }

    uint32_t lane_x1 = (uint32_t)(lane ^ ((lane >> 3) & 1));

    float4 va[4], vbr[2];
    // prologue: chunk 0 -> buf 0
#pragma unroll
    for (int p = 0; p < 4; p++)
        va[p] = (doA[p] && ap[p]) ? *(const float4*)(ap[p]) : make_float4(0.f, 0.f, 0.f, 0.f);
#pragma unroll
    for (int p = 0; p < 2; p++) vbr[p] = *(const float4*)(bp[p]);
#pragma unroll
    for (int p = 0; p < 4; p++) if (doA[p]) sts_frag4(sb + aoff[p], ajo, va[p]);
#pragma unroll
    for (int p = 0; p < 2; p++) sts_frag4(sb + boff[p], bjo, vbr[p]);
    __syncthreads();

#pragma unroll 1
    for (int kc = 0; kc < NC1; kc++) {
        int buf = kc & 1;
        if (kc + 1 < NC1) {
            int ko = (kc + 1) * BK;
#pragma unroll
            for (int p = 0; p < 4; p++)
                va[p] = (doA[p] && ap[p]) ? *(const float4*)(ap[p] + ko) : make_float4(0.f, 0.f, 0.f, 0.f);
#pragma unroll
            for (int p = 0; p < 2; p++) vbr[p] = *(const float4*)(bp[p] + ko);
        }
        uint32_t Ab = sb + buf * STG;
        uint32_t Bb = Ab + A_FRAG_BYTES;
#pragma unroll
        for (int ks = 0; ks < 4; ks++) {
            uint32_t aL = Ab + ks * 512 + ((lane_x1 ^ (uint32_t)ks) << 4);
            uint32_t bL = Bb + ks * 256 + (((uint32_t)lane ^ (uint32_t)ks) << 3);
            uint32_t b1v[2][2], b2v[2][2];
#pragma unroll
            for (int nt = 0; nt < 2; nt++) {
                lds64(b1v[nt], bL + (uint32_t)((wn * 2 + nt) * 1024));
                lds64(b2v[nt], bL + (uint32_t)((8 + wn * 2 + nt) * 1024));
            }
#pragma unroll
            for (int mt = 0; mt < 4; mt++) {
                if (mt < mt_lim) {
                    uint32_t a[4];
                    lds128(a, aL + (uint32_t)((wm * 4 + mt) * 2048));
#pragma unroll
                    for (int nt = 0; nt < 2; nt++) {
                        MMA_TF32(acc1[mt][nt], a, b1v[nt][0], b1v[nt][1]);
                        MMA_TF32(acc2[mt][nt], a, b2v[nt][0], b2v[nt][1]);
                    }
                }
            }
        }
        if (kc + 1 < NC1) {
            uint32_t base2 = sb + (uint32_t)((buf ^ 1) * STG);
#pragma unroll
            for (int p = 0; p < 4; p++) if (doA[p]) sts_frag4(base2 + aoff[p], ajo, va[p]);
#pragma unroll
            for (int p = 0; p < 2; p++) sts_frag4(base2 + boff[p], bjo, vbr[p]);
        }
        __syncthreads();
    }

    // epilogue: fused SwiGLU
#pragma unroll
    for (int mt = 0; mt < 4; mt++) {
        int rbase = m0 + wm * 64 + mt * 16 + lq;
#pragma unroll
        for (int nt = 0; nt < 2; nt++) {
            int col = n0 + wn * 16 + nt * 8 + lr * 2;
#pragma unroll
            for (int half = 0; half < 2; half++) {
                int r = rbase + half * 8;
                if (r < M) {
                    float g1a = acc1[mt][nt][half * 2 + 0];
                    float g1b = acc1[mt][nt][half * 2 + 1];
                    float g2a = acc2[mt][nt][half * 2 + 0];
                    float g2b = acc2[mt][nt][half * 2 + 1];
                    float2 o;
                    o.x = g1a * (g2a / (1.f + expf(-g2a)));
                    o.y = g1b * (g2b / (1.f + expf(-g2b)));
                    *(float2*)&Out[(size_t)r * I1 + col] = o;
                }
            }
        }
    }
}

// ---------------- GEMM2 (tf32 mma.sync, frag-order smem): 256 x 128 ----------------
__global__ __launch_bounds__(512, 1)
void gemm2_mma(const float* __restrict__ Wd, float* __restrict__ dout, int shared_mode) {
    int e = blockIdx.z;
    int M; const float* G; const float* Wp; float* Out;
    if (shared_mode) { M = S_TOK; G = &g_sh_gated[0][0]; Wp = Wd; Out = dout; }
    else {
        M = g_ecount[e]; G = &g_ex_gated[e][0][0];
        Wp = Wd + (size_t)e * HID * I1; Out = &g_ex_out[e][0][0];
    }
    int m0 = blockIdx.y * BM;
    if (m0 >= M) return;
    int n0 = blockIdx.x * 128;
    int Mrem = M - m0;
    int Mceil = (Mrem + 15) & ~15;

    uint32_t sb = smem_u32(dsm);
    int t = threadIdx.x, lane = t & 31, wid = t >> 5;
    int wm = wid >> 2, wn = wid & 3;     // warp = 64 rows x 32 cols
    int lq = lane >> 2, lr = lane & 3;

    int wrem = Mrem - wm * 64;
    int mt_lim = (wrem >= 64) ? 4 : ((wrem <= 0) ? 0 : ((wrem + 15) >> 4));

    int kseg = t & 7;
    int r64  = t >> 3;
    int ksw  = kseg >> 1;
    int gID  = r64 & 7;
    int regA = ((r64 >> 3) & 1) + 2 * (kseg & 1);
    int swzA = ksw ^ ((gID >> 1) & 1);

    uint32_t aoff[4], ajo[4], bjo[4];
#pragma unroll
    for (int p = 0; p < 4; p++)
        aoff[p] = (uint32_t)((p * 4 + (r64 >> 4)) * 2048 + ksw * 512 + gID * 64 + regA * 4);
#pragma unroll
    for (int j = 0; j < 4; j++) { ajo[j] = (uint32_t)((j ^ swzA) << 4); bjo[j] = (uint32_t)((j ^ ksw) << 3); }
    uint32_t boff[2];
#pragma unroll
    for (int p = 0; p < 2; p++)
        boff[p] = (uint32_t)(A_FRAG_BYTES + (p * 8 + (r64 >> 3)) * 1024 + ksw * 256 + gID * 32 + (kseg & 1) * 4);

    bool doA[4];
    const float* ap[4];
#pragma unroll
    for (int p = 0; p < 4; p++) {
        doA[p] = (p * 64) < Mceil;
        int m = m0 + p * 64 + r64;
        ap[p] = (m < M) ? (G + (size_t)m * I1 + kseg * 4) : nullptr;
    }
    const float* bp[2];
    bp[0] = Wp + (size_t)(n0 + r64) * I1 + kseg * 4;
    bp[1] = Wp + (size_t)(n0 + 64 + r64) * I1 + kseg * 4;

    float acc[4][4][4];
#pragma unroll
    for (int mt = 0; mt < 4; mt++)
#pragma unroll
        for (int nt = 0; nt < 4; nt++)
#pragma unroll
            for (int i = 0; i < 4; i++) acc[mt][nt][i] = 0.f;

    uint32_t lane_x1 = (uint32_t)(lane ^ ((lane >> 3) & 1));

    float4 va[4], vbr[2];
#pragma unroll
    for (int p = 0; p < 4; p++)
        va[p] = (doA[p] && ap[p]) ? *(const float4*)(ap[p]) : make_float4(0.f, 0.f, 0.f, 0.f);
#pragma unroll
    for (int p = 0; p < 2; p++) vbr[p] = *(const float4*)(bp[p]);
#pragma unroll
    for (int p = 0; p < 4; p++) if (doA[p]) sts_frag4(sb + aoff[p], ajo, va[p]);
#pragma unroll
    for (int p = 0; p < 2; p++) sts_frag4(sb + boff[p], bjo, vbr[p]);
    __syncthreads();

#pragma unroll 1
    for (int kc = 0; kc < NC2; kc++) {
        int buf = kc & 1;
        if (kc + 1 < NC2) {
            int ko = (kc + 1) * BK;
#pragma unroll
            for (int p = 0; p < 4; p++)
                va[p] = (doA[p] && ap[p]) ? *(const float4*)(ap[p] + ko) : make_float4(0.f, 0.f, 0.f, 0.f);
#pragma unroll
            for (int p = 0; p < 2; p++) vbr[p] = *(const float4*)(bp[p] + ko);
        }
        uint32_t Ab = sb + buf * STG;
        uint32_t Bb = Ab + A_FRAG_BYTES;
#pragma unroll
        for (int ks = 0; ks < 4; ks++) {
            uint32_t aL = Ab + ks * 512 + ((lane_x1 ^ (uint32_t)ks) << 4);
            uint32_t bL = Bb + ks * 256 + (((uint32_t)lane ^ (uint32_t)ks) << 3);
            uint32_t bv[4][2];
#pragma unroll
            for (int nt = 0; nt < 4; nt++)
                lds64(bv[nt], bL + (uint32_t)((wn * 4 + nt) * 1024));
#pragma unroll
            for (int mt = 0; mt < 4; mt++) {
                if (mt < mt_lim) {
                    uint32_t a[4];
                    lds128(a, aL + (uint32_t)((wm * 4 + mt) * 2048));
#pragma unroll
                    for (int nt = 0; nt < 4; nt++)
                        MMA_TF32(acc[mt][nt], a, bv[nt][0], bv[nt][1]);
                }
            }
        }
        if (kc + 1 < NC2) {
            uint32_t base2 = sb + (uint32_t)((buf ^ 1) * STG);
#pragma unroll
            for (int p = 0; p < 4; p++) if (doA[p]) sts_frag4(base2 + aoff[p], ajo, va[p]);
#pragma unroll
            for (int p = 0; p < 2; p++) sts_frag4(base2 + boff[p], bjo, vbr[p]);
        }
        __syncthreads();
    }

#pragma unroll
    for (int mt = 0; mt < 4; mt++) {
        int rbase = m0 + wm * 64 + mt * 16 + lq;
#pragma unroll
        for (int nt = 0; nt < 4; nt++) {
            int col = n0 + wn * 32 + nt * 8 + lr * 2;
#pragma unroll
            for (int half = 0; half < 2; half++) {
                int r = rbase + half * 8;
                if (r < M) {
                    float2 o;
                    o.x = acc[mt][nt][half * 2 + 0];
                    o.y = acc[mt][nt][half * 2 + 1];
                    *(float2*)&Out[(size_t)r * HID + col] = o;
                }
            }
        }
    }
}

// ---------------- combine ----------------
__global__ void combine_kernel(float* __restrict__ out) {
    int s = blockIdx.x, tid = threadIdx.x;
    __shared__ int ke[TK], kc_[TK];
    __shared__ float kw[TK];
    if (tid < TK) { ke[tid] = g_topi[s][tid]; kc_[tid] = g_slot[s][tid]; kw[tid] = g_topw[s][tid]; }
    __syncthreads();
    for (int h = tid; h < HID; h += 256) {
        float acc = out[(size_t)s * HID + h];
#pragma unroll
        for (int k = 0; k < TK; k++) {
            int c = kc_[k];
            if (c >= 0) acc += kw[k] * g_ex_out[ke[k]][c][h];
        }
        out[(size_t)s * HID + h] = acc;
    }
}

// ---------------------------------------------------------------------------
extern "C" void kernel_launch(void* const* d_in, const int* in_sizes, int n_in,
                              void* d_out, int out_size) {
    const float* x      = (const float*)d_in[0];
    const float* w_gu   = (const float*)d_in[1];
    const float* w_down = (const float*)d_in[2];
    const float* wg     = (const float*)d_in[3];
    const float* w1     = (const float*)d_in[4];
    const float* w2     = (const float*)d_in[5];
    const int*   cap    = (const int*)d_in[6];
    float* out = (float*)d_out;

    cudaFuncSetAttribute(gemm1_mma, cudaFuncAttributeMaxDynamicSharedMemorySize, SMEM_BYTES);
    cudaFuncSetAttribute(gemm2_mma, cudaFuncAttributeMaxDynamicSharedMemorySize, SMEM_BYTES);

    gating_kernel<<<S_TOK, 256>>>(x, wg);
    priority_kernel<<<NE, 32>>>(cap);

    { dim3 g(I1 / 64, S_TOK / BM, 1);    gemm1_mma<<<g, 512, SMEM_BYTES>>>(x, w_gu, 1); }
    { dim3 g(I1 / 64, 1, NE);            gemm1_mma<<<g, 512, SMEM_BYTES>>>(x, w1, 0); }
    { dim3 g(HID / 128, S_TOK / BM, 1);  gemm2_mma<<<g, 512, SMEM_BYTES>>>(w_down, out, 1); }
    { dim3 g(HID / 128, 1, NE);          gemm2_mma<<<g, 512, SMEM_BYTES>>>(w2, out, 0); }

    combine_kernel<<<S_TOK, 256>>>(out);
}

// round 6
// speedup vs baseline: 1.3190x; 1.3190x over previous
#include <cuda_runtime.h>
#include <cstdint>
#include <math.h>

// ---------------- problem constants ----------------
#define S_TOK   1024
#define HID     768
#define NE      64
#define TK      8
#define CAPMAX  256
#define I1      3072
#define I2      6144

// ---------------- GEMM tiling ----------------
#define BM   128
#define BK   32
#define PR   36                        // padded row length (floats)
#define A_BYTES (BM * PR * 4)          // 18432
#define B_BYTES (128 * PR * 4)         // 18432
#define STG     (A_BYTES + B_BYTES)    // 36864
#define SMEM_BYTES (2 * STG)           // 73728
#define NC1 (HID / BK)                 // 24
#define NC2 (I1 / BK)                  // 96

// ---------------- device scratch ----------------
__device__ __align__(16)  float g_topw[S_TOK][TK];
__device__ __align__(16)  int   g_topi[S_TOK][TK];
__device__ __align__(16)  int   g_slot[S_TOK][TK];
__device__ __align__(16)  int   g_ecount[NE];
__device__ __align__(16)  int   g_etok[NE][CAPMAX];
__device__ __align__(256) float g_sh_gated[S_TOK][I1];
__device__ __align__(256) float g_ex_gated[NE][CAPMAX][I1];
__device__ __align__(256) float g_ex_out[NE][CAPMAX][HID];

// ---------------- helpers ----------------
__device__ __forceinline__ uint32_t smem_u32(const void* p) {
    uint32_t a;
    asm("{ .reg .u64 t; cvta.to.shared.u64 t, %1; cvt.u32.u64 %0, t; }" : "=r"(a) : "l"(p));
    return a;
}
__device__ __forceinline__ uint32_t lds_u32(uint32_t addr) {
    uint32_t v;
    asm volatile("ld.shared.b32 %0, [%1];" : "=r"(v) : "r"(addr));
    return v;
}
__device__ __forceinline__ void cvt_sts(uint32_t addr, float4 v) {
    uint32_t a, b, c, d;
    asm volatile("cvt.rna.tf32.f32 %0, %1;" : "=r"(a) : "f"(v.x));
    asm volatile("cvt.rna.tf32.f32 %0, %1;" : "=r"(b) : "f"(v.y));
    asm volatile("cvt.rna.tf32.f32 %0, %1;" : "=r"(c) : "f"(v.z));
    asm volatile("cvt.rna.tf32.f32 %0, %1;" : "=r"(d) : "f"(v.w));
    asm volatile("st.shared.v4.b32 [%0], {%1, %2, %3, %4};"
                 :: "r"(addr), "r"(a), "r"(b), "r"(c), "r"(d) : "memory");
}
#define MMA_TF32(c, a, b0v, b1v) \
    asm volatile("mma.sync.aligned.m16n8k8.row.col.f32.tf32.tf32.f32 " \
        "{%0,%1,%2,%3}, {%4,%5,%6,%7}, {%8,%9}, {%0,%1,%2,%3};" \
        : "+f"((c)[0]), "+f"((c)[1]), "+f"((c)[2]), "+f"((c)[3]) \
        : "r"((a)[0]), "r"((a)[1]), "r"((a)[2]), "r"((a)[3]), "r"(b0v), "r"(b1v))

extern __shared__ char dsm[];

// ---------------- gating ----------------
__global__ void gating_kernel(const float* __restrict__ x,
                              const float* __restrict__ wg) {
    int s = blockIdx.x;
    __shared__ float xs[HID];
    __shared__ float logits_s[NE];
    int tid = threadIdx.x;

    for (int i = tid; i < HID; i += 256) xs[i] = x[(size_t)s * HID + i];
    __syncthreads();

    int e = tid >> 2, sub = tid & 3;
    const float* w = wg + (size_t)e * HID;
    float acc = 0.f;
    for (int i = sub; i < HID; i += 4) acc += xs[i] * w[i];
    acc += __shfl_down_sync(0xffffffffu, acc, 2);
    acc += __shfl_down_sync(0xffffffffu, acc, 1);
    if (sub == 0) logits_s[e] = acc;
    __syncthreads();

    if (tid < 32) {
        float v0 = logits_s[tid];
        float v1 = logits_s[tid + 32];
        float tv[TK]; int tix[TK];
#pragma unroll
        for (int r = 0; r < TK; r++) {
            float bv; int bi;
            if (v0 >= v1) { bv = v0; bi = tid; }
            else          { bv = v1; bi = tid + 32; }
#pragma unroll
            for (int off = 16; off > 0; off >>= 1) {
                float ov = __shfl_down_sync(0xffffffffu, bv, off);
                int   oi = __shfl_down_sync(0xffffffffu, bi, off);
                if (ov > bv || (ov == bv && oi < bi)) { bv = ov; bi = oi; }
            }
            bv = __shfl_sync(0xffffffffu, bv, 0);
            bi = __shfl_sync(0xffffffffu, bi, 0);
            if (bi == tid)      v0 = -INFINITY;
            if (bi == tid + 32) v1 = -INFINITY;
            tv[r] = bv; tix[r] = bi;
        }
        if (tid == 0) {
            float m = tv[0], wv[TK], D = 0.f;
#pragma unroll
            for (int r = 0; r < TK; r++) { wv[r] = expf(tv[r] - m); D += wv[r]; }
            D = fmaxf(D, 1.1920929e-7f);
#pragma unroll
            for (int r = 0; r < TK; r++) { g_topw[s][r] = wv[r] / D; g_topi[s][r] = tix[r]; }
        }
    }
}

// ---------------- priority ----------------
__global__ void priority_kernel(const int* __restrict__ capacity) {
    int e = blockIdx.x, lane = threadIdx.x;
    int cap = capacity[0];
    if (cap > CAPMAX) cap = CAPMAX;
    if (cap < 0) cap = 0;

    int offset = 0;
    for (int base = 0; base < S_TOK * TK; base += 32) {
        int p = base + lane;
        int k = p / S_TOK;
        int s = p - k * S_TOK;
        bool match = (g_topi[s][k] == e);
        unsigned mask = __ballot_sync(0xffffffffu, match);
        if (match) {
            int c = offset + __popc(mask & ((1u << lane) - 1u));
            if (c < cap) { g_slot[s][k] = c; g_etok[e][c] = s; }
            else         { g_slot[s][k] = -1; }
        }
        offset += __popc(mask);
    }
    if (lane == 0) g_ecount[e] = (offset < cap) ? offset : cap;
}

// ---------------- GEMM1 (tf32 mma.sync, 256 thr, BM=128) + SwiGLU ----------------
// Block: 128 rows x 64 output cols (pair: g1 + g2). 8 warps 2(M)x4(N).
// B smem rows 0..63 = g1 W rows, 64..127 = g2 W rows.
__global__ __launch_bounds__(256, 2)
void gemm1_mma(const float* __restrict__ X, const float* __restrict__ W, int shared_mode) {
    int e = blockIdx.z;
    int M; const int* gather; const float* Wp; float* Out;
    if (shared_mode) { M = S_TOK; gather = nullptr; Wp = W; Out = &g_sh_gated[0][0]; }
    else {
        M = g_ecount[e]; gather = g_etok[e];
        Wp = W + (size_t)e * I2 * HID; Out = &g_ex_gated[e][0][0];
    }
    int m0 = blockIdx.y * BM;
    if (m0 >= M) return;
    int n0 = blockIdx.x * 64;

    uint32_t sb = smem_u32(dsm);
    int t = threadIdx.x, lane = t & 31, wid = t >> 5;
    int wm = wid >> 2, wn = wid & 3;     // 2 x 4 warp grid; warp = 64 rows x 16 cols
    int lq = lane >> 2, lr = lane & 3;

    int kseg = t & 7;           // k offset kseg*4
    int r32  = t >> 3;          // 0..31 row within pass

    // A: 4 passes of 32 rows
    const float* ap[4];
#pragma unroll
    for (int p = 0; p < 4; p++) {
        int m = m0 + p * 32 + r32;
        ap[p] = (m < M) ? (X + (size_t)(gather ? gather[m] : m) * HID + kseg * 4) : nullptr;
    }
    // B: 4 passes of 32 rows (rows<64 -> g1, else g2)
    const float* bp[4];
#pragma unroll
    for (int p = 0; p < 4; p++) {
        int row = p * 32 + r32;
        int wr = (row < 64) ? (n0 + row) : (n0 + row - 64 + I1);
        bp[p] = Wp + (size_t)wr * HID + kseg * 4;
    }

    float acc1[4][2][4], acc2[4][2][4];
#pragma unroll
    for (int mt = 0; mt < 4; mt++)
#pragma unroll
        for (int nt = 0; nt < 2; nt++)
#pragma unroll
            for (int i = 0; i < 4; i++) { acc1[mt][nt][i] = 0.f; acc2[mt][nt][i] = 0.f; }

    float4 va[4], vbr[4];
    uint32_t sts_off = (uint32_t)(r32 * PR + kseg * 4) * 4;

    // prologue: chunk 0 -> buf 0
#pragma unroll
    for (int p = 0; p < 4; p++)
        va[p] = ap[p] ? *(const float4*)(ap[p]) : make_float4(0.f, 0.f, 0.f, 0.f);
#pragma unroll
    for (int p = 0; p < 4; p++) vbr[p] = *(const float4*)(bp[p]);
    {
        uint32_t Ab = sb, Bb = sb + A_BYTES;
#pragma unroll
        for (int p = 0; p < 4; p++) cvt_sts(Ab + p * 32 * PR * 4 + sts_off, va[p]);
#pragma unroll
        for (int p = 0; p < 4; p++) cvt_sts(Bb + p * 32 * PR * 4 + sts_off, vbr[p]);
    }
    __syncthreads();

#pragma unroll 1
    for (int kc = 0; kc < NC1; kc++) {
        int buf = kc & 1;
        if (kc + 1 < NC1) {
            int ko = (kc + 1) * BK;
#pragma unroll
            for (int p = 0; p < 4; p++)
                va[p] = ap[p] ? *(const float4*)(ap[p] + ko) : make_float4(0.f, 0.f, 0.f, 0.f);
#pragma unroll
            for (int p = 0; p < 4; p++) vbr[p] = *(const float4*)(bp[p] + ko);
        }
        uint32_t Ab = sb + buf * STG;
        uint32_t Bb = Ab + A_BYTES;
#pragma unroll
        for (int ks = 0; ks < 4; ks++) {
            uint32_t kcol = (uint32_t)(ks * 8 + lr) * 4;
            uint32_t b1v[2][2], b2v[2][2];
#pragma unroll
            for (int nt = 0; nt < 2; nt++) {
                uint32_t base1 = Bb + (uint32_t)((wn * 16 + nt * 8 + lq) * PR) * 4 + kcol;
                b1v[nt][0] = lds_u32(base1);
                b1v[nt][1] = lds_u32(base1 + 16);
                uint32_t base2 = base1 + 64 * PR * 4;
                b2v[nt][0] = lds_u32(base2);
                b2v[nt][1] = lds_u32(base2 + 16);
            }
#pragma unroll
            for (int mt = 0; mt < 4; mt++) {
                uint32_t a[4];
                uint32_t base = Ab + (uint32_t)((wm * 64 + mt * 16 + lq) * PR) * 4 + kcol;
                a[0] = lds_u32(base);
                a[1] = lds_u32(base + 8 * PR * 4);
                a[2] = lds_u32(base + 16);
                a[3] = lds_u32(base + 8 * PR * 4 + 16);
#pragma unroll
                for (int nt = 0; nt < 2; nt++) {
                    MMA_TF32(acc1[mt][nt], a, b1v[nt][0], b1v[nt][1]);
                    MMA_TF32(acc2[mt][nt], a, b2v[nt][0], b2v[nt][1]);
                }
            }
        }
        if (kc + 1 < NC1) {
            uint32_t Ab2 = sb + (buf ^ 1) * STG;
            uint32_t Bb2 = Ab2 + A_BYTES;
#pragma unroll
            for (int p = 0; p < 4; p++) cvt_sts(Ab2 + p * 32 * PR * 4 + sts_off, va[p]);
#pragma unroll
            for (int p = 0; p < 4; p++) cvt_sts(Bb2 + p * 32 * PR * 4 + sts_off, vbr[p]);
        }
        __syncthreads();
    }

    // epilogue: fused SwiGLU
#pragma unroll
    for (int mt = 0; mt < 4; mt++) {
        int rbase = m0 + wm * 64 + mt * 16 + lq;
#pragma unroll
        for (int nt = 0; nt < 2; nt++) {
            int col = n0 + wn * 16 + nt * 8 + lr * 2;
#pragma unroll
            for (int half = 0; half < 2; half++) {
                int r = rbase + half * 8;
                if (r < M) {
                    float g1a = acc1[mt][nt][half * 2 + 0];
                    float g1b = acc1[mt][nt][half * 2 + 1];
                    float g2a = acc2[mt][nt][half * 2 + 0];
                    float g2b = acc2[mt][nt][half * 2 + 1];
                    float2 o;
                    o.x = g1a * (g2a / (1.f + expf(-g2a)));
                    o.y = g1b * (g2b / (1.f + expf(-g2b)));
                    *(float2*)&Out[(size_t)r * I1 + col] = o;
                }
            }
        }
    }
}

// ---------------- GEMM2 (tf32 mma.sync, 256 thr): 128 x 128 tile ----------------
__global__ __launch_bounds__(256, 2)
void gemm2_mma(const float* __restrict__ Wd, float* __restrict__ dout, int shared_mode) {
    int e = blockIdx.z;
    int M; const float* G; const float* Wp; float* Out;
    if (shared_mode) { M = S_TOK; G = &g_sh_gated[0][0]; Wp = Wd; Out = dout; }
    else {
        M = g_ecount[e]; G = &g_ex_gated[e][0][0];
        Wp = Wd + (size_t)e * HID * I1; Out = &g_ex_out[e][0][0];
    }
    int m0 = blockIdx.y * BM;
    if (m0 >= M) return;
    int n0 = blockIdx.x * 128;

    uint32_t sb = smem_u32(dsm);
    int t = threadIdx.x, lane = t & 31, wid = t >> 5;
    int wm = wid >> 2, wn = wid & 3;     // warp = 64 rows x 32 cols
    int lq = lane >> 2, lr = lane & 3;

    int kseg = t & 7;
    int r32  = t >> 3;

    const float* ap[4];
#pragma unroll
    for (int p = 0; p < 4; p++) {
        int m = m0 + p * 32 + r32;
        ap[p] = (m < M) ? (G + (size_t)m * I1 + kseg * 4) : nullptr;
    }
    const float* bp[4];
#pragma unroll
    for (int p = 0; p < 4; p++)
        bp[p] = Wp + (size_t)(n0 + p * 32 + r32) * I1 + kseg * 4;

    float acc[4][4][4];
#pragma unroll
    for (int mt = 0; mt < 4; mt++)
#pragma unroll
        for (int nt = 0; nt < 4; nt++)
#pragma unroll
            for (int i = 0; i < 4; i++) acc[mt][nt][i] = 0.f;

    float4 va[4], vbr[4];
    uint32_t sts_off = (uint32_t)(r32 * PR + kseg * 4) * 4;

#pragma unroll
    for (int p = 0; p < 4; p++)
        va[p] = ap[p] ? *(const float4*)(ap[p]) : make_float4(0.f, 0.f, 0.f, 0.f);
#pragma unroll
    for (int p = 0; p < 4; p++) vbr[p] = *(const float4*)(bp[p]);
    {
        uint32_t Ab = sb, Bb = sb + A_BYTES;
#pragma unroll
        for (int p = 0; p < 4; p++) cvt_sts(Ab + p * 32 * PR * 4 + sts_off, va[p]);
#pragma unroll
        for (int p = 0; p < 4; p++) cvt_sts(Bb + p * 32 * PR * 4 + sts_off, vbr[p]);
    }
    __syncthreads();

#pragma unroll 1
    for (int kc = 0; kc < NC2; kc++) {
        int buf = kc & 1;
        if (kc + 1 < NC2) {
            int ko = (kc + 1) * BK;
#pragma unroll
            for (int p = 0; p < 4; p++)
                va[p] = ap[p] ? *(const float4*)(ap[p] + ko) : make_float4(0.f, 0.f, 0.f, 0.f);
#pragma unroll
            for (int p = 0; p < 4; p++) vbr[p] = *(const float4*)(bp[p] + ko);
        }
        uint32_t Ab = sb + buf * STG;
        uint32_t Bb = Ab + A_BYTES;
#pragma unroll
        for (int ks = 0; ks < 4; ks++) {
            uint32_t kcol = (uint32_t)(ks * 8 + lr) * 4;
            uint32_t bv[4][2];
#pragma unroll
            for (int nt = 0; nt < 4; nt++) {
                uint32_t base = Bb + (uint32_t)((wn * 32 + nt * 8 + lq) * PR) * 4 + kcol;
                bv[nt][0] = lds_u32(base);
                bv[nt][1] = lds_u32(base + 16);
            }
#pragma unroll
            for (int mt = 0; mt < 4; mt++) {
                uint32_t a[4];
                uint32_t base = Ab + (uint32_t)((wm * 64 + mt * 16 + lq) * PR) * 4 + kcol;
                a[0] = lds_u32(base);
                a[1] = lds_u32(base + 8 * PR * 4);
                a[2] = lds_u32(base + 16);
                a[3] = lds_u32(base + 8 * PR * 4 + 16);
#pragma unroll
                for (int nt = 0; nt < 4; nt++)
                    MMA_TF32(acc[mt][nt], a, bv[nt][0], bv[nt][1]);
            }
        }
        if (kc + 1 < NC2) {
            uint32_t Ab2 = sb + (buf ^ 1) * STG;
            uint32_t Bb2 = Ab2 + A_BYTES;
#pragma unroll
            for (int p = 0; p < 4; p++) cvt_sts(Ab2 + p * 32 * PR * 4 + sts_off, va[p]);
#pragma unroll
            for (int p = 0; p < 4; p++) cvt_sts(Bb2 + p * 32 * PR * 4 + sts_off, vbr[p]);
        }
        __syncthreads();
    }

#pragma unroll
    for (int mt = 0; mt < 4; mt++) {
        int rbase = m0 + wm * 64 + mt * 16 + lq;
#pragma unroll
        for (int nt = 0; nt < 4; nt++) {
            int col = n0 + wn * 32 + nt * 8 + lr * 2;
#pragma unroll
            for (int half = 0; half < 2; half++) {
                int r = rbase + half * 8;
                if (r < M) {
                    float2 o;
                    o.x = acc[mt][nt][half * 2 + 0];
                    o.y = acc[mt][nt][half * 2 + 1];
                    *(float2*)&Out[(size_t)r * HID + col] = o;
                }
            }
        }
    }
}

// ---------------- combine ----------------
__global__ void combine_kernel(float* __restrict__ out) {
    int s = blockIdx.x, tid = threadIdx.x;
    __shared__ int ke[TK], kc_[TK];
    __shared__ float kw[TK];
    if (tid < TK) { ke[tid] = g_topi[s][tid]; kc_[tid] = g_slot[s][tid]; kw[tid] = g_topw[s][tid]; }
    __syncthreads();
    for (int h = tid; h < HID; h += 256) {
        float acc = out[(size_t)s * HID + h];
#pragma unroll
        for (int k = 0; k < TK; k++) {
            int c = kc_[k];
            if (c >= 0) acc += kw[k] * g_ex_out[ke[k]][c][h];
        }
        out[(size_t)s * HID + h] = acc;
    }
}

// ---------------------------------------------------------------------------
extern "C" void kernel_launch(void* const* d_in, const int* in_sizes, int n_in,
                              void* d_out, int out_size) {
    const float* x      = (const float*)d_in[0];
    const float* w_gu   = (const float*)d_in[1];
    const float* w_down = (const float*)d_in[2];
    const float* wg     = (const float*)d_in[3];
    const float* w1     = (const float*)d_in[4];
    const float* w2     = (const float*)d_in[5];
    const int*   cap    = (const int*)d_in[6];
    float* out = (float*)d_out;

    cudaFuncSetAttribute(gemm1_mma, cudaFuncAttributeMaxDynamicSharedMemorySize, SMEM_BYTES);
    cudaFuncSetAttribute(gemm2_mma, cudaFuncAttributeMaxDynamicSharedMemorySize, SMEM_BYTES);

    gating_kernel<<<S_TOK, 256>>>(x, wg);
    priority_kernel<<<NE, 32>>>(cap);

    { dim3 g(I1 / 64, S_TOK / BM, 1);       gemm1_mma<<<g, 256, SMEM_BYTES>>>(x, w_gu, 1); }
    { dim3 g(I1 / 64, CAPMAX / BM, NE);     gemm1_mma<<<g, 256, SMEM_BYTES>>>(x, w1, 0); }
    { dim3 g(HID / 128, S_TOK / BM, 1);     gemm2_mma<<<g, 256, SMEM_BYTES>>>(w_down, out, 1); }
    { dim3 g(HID / 128, CAPMAX / BM, NE);   gemm2_mma<<<g, 256, SMEM_BYTES>>>(w2, out, 0); }

    combine_kernel<<<S_TOK, 256>>>(out);
}

// round 7
// speedup vs baseline: 1.4066x; 1.0664x over previous
#include <cuda_runtime.h>
#include <cstdint>
#include <math.h>

// ---------------- problem constants ----------------
#define S_TOK   1024
#define HID     768
#define NE      64
#define TK      8
#define CAPMAX  256
#define I1      3072
#define I2      6144

// ---------------- GEMM tiling ----------------
#define BM   128
#define BK   32
#define PR   36                        // padded row length (floats)
#define A_BYTES (BM * PR * 4)          // 18432
#define B_BYTES (128 * PR * 4)         // 18432
#define STG     (A_BYTES + B_BYTES)    // 36864
#define SMEM_BYTES (2 * STG)           // 73728
#define NC1 (HID / BK)                 // 24
#define NC2 (I1 / BK)                  // 96

// merged-grid sizes
#define G1_EXP_BLKS (48 * 2 * NE)      // 6144
#define G1_SH_BLKS  (48 * 8)           // 384
#define G2_EXP_BLKS (6 * 2 * NE)       // 768
#define G2_SH_BLKS  (6 * 8)            // 48

// ---------------- device scratch ----------------
__device__ __align__(16)  float g_topw[S_TOK][TK];
__device__ __align__(16)  int   g_topi[S_TOK][TK];
__device__ __align__(16)  int   g_slot[S_TOK][TK];
__device__ __align__(16)  int   g_ecount[NE];
__device__ __align__(16)  int   g_etok[NE][CAPMAX];
__device__ __align__(256) float g_sh_gated[S_TOK][I1];
__device__ __align__(256) float g_ex_gated[NE][CAPMAX][I1];
__device__ __align__(256) float g_ex_out[NE][CAPMAX][HID];

// ---------------- helpers ----------------
__device__ __forceinline__ uint32_t smem_u32(const void* p) {
    uint32_t a;
    asm("{ .reg .u64 t; cvta.to.shared.u64 t, %1; cvt.u32.u64 %0, t; }" : "=r"(a) : "l"(p));
    return a;
}
__device__ __forceinline__ uint32_t lds_u32(uint32_t addr) {
    uint32_t v;
    asm volatile("ld.shared.b32 %0, [%1];" : "=r"(v) : "r"(addr));
    return v;
}
// convert 4 fp32 -> tf32 (RNA) and store 16B to smem
__device__ __forceinline__ void cvt_sts(uint32_t addr, float4 v) {
    uint32_t a, b, c, d;
    asm volatile("cvt.rna.tf32.f32 %0, %1;" : "=r"(a) : "f"(v.x));
    asm volatile("cvt.rna.tf32.f32 %0, %1;" : "=r"(b) : "f"(v.y));
    asm volatile("cvt.rna.tf32.f32 %0, %1;" : "=r"(c) : "f"(v.z));
    asm volatile("cvt.rna.tf32.f32 %0, %1;" : "=r"(d) : "f"(v.w));
    asm volatile("st.shared.v4.b32 [%0], {%1, %2, %3, %4};"
                 :: "r"(addr), "r"(a), "r"(b), "r"(c), "r"(d) : "memory");
}
// raw store (data already tf32-rounded)
__device__ __forceinline__ void raw_sts(uint32_t addr, float4 v) {
    asm volatile("st.shared.v4.b32 [%0], {%1, %2, %3, %4};"
                 :: "r"(addr), "r"(__float_as_uint(v.x)), "r"(__float_as_uint(v.y)),
                    "r"(__float_as_uint(v.z)), "r"(__float_as_uint(v.w)) : "memory");
}
__device__ __forceinline__ float tf32r(float x) {
    uint32_t v;
    asm("cvt.rna.tf32.f32 %0, %1;" : "=r"(v) : "f"(x));
    return __uint_as_float(v);
}
#define MMA_TF32(c, a, b0v, b1v) \
    asm volatile("mma.sync.aligned.m16n8k8.row.col.f32.tf32.tf32.f32 " \
        "{%0,%1,%2,%3}, {%4,%5,%6,%7}, {%8,%9}, {%0,%1,%2,%3};" \
        : "+f"((c)[0]), "+f"((c)[1]), "+f"((c)[2]), "+f"((c)[3]) \
        : "r"((a)[0]), "r"((a)[1]), "r"((a)[2]), "r"((a)[3]), "r"(b0v), "r"(b1v))

extern __shared__ char dsm[];

// ---------------- gating ----------------
__global__ void gating_kernel(const float* __restrict__ x,
                              const float* __restrict__ wg) {
    int s = blockIdx.x;
    __shared__ float xs[HID];
    __shared__ float logits_s[NE];
    int tid = threadIdx.x;

    for (int i = tid; i < HID; i += 256) xs[i] = x[(size_t)s * HID + i];
    __syncthreads();

    int e = tid >> 2, sub = tid & 3;
    const float* w = wg + (size_t)e * HID;
    float acc = 0.f;
    for (int i = sub; i < HID; i += 4) acc += xs[i] * w[i];
    acc += __shfl_down_sync(0xffffffffu, acc, 2);
    acc += __shfl_down_sync(0xffffffffu, acc, 1);
    if (sub == 0) logits_s[e] = acc;
    __syncthreads();

    if (tid < 32) {
        float v0 = logits_s[tid];
        float v1 = logits_s[tid + 32];
        float tv[TK]; int tix[TK];
#pragma unroll
        for (int r = 0; r < TK; r++) {
            float bv; int bi;
            if (v0 >= v1) { bv = v0; bi = tid; }
            else          { bv = v1; bi = tid + 32; }
#pragma unroll
            for (int off = 16; off > 0; off >>= 1) {
                float ov = __shfl_down_sync(0xffffffffu, bv, off);
                int   oi = __shfl_down_sync(0xffffffffu, bi, off);
                if (ov > bv || (ov == bv && oi < bi)) { bv = ov; bi = oi; }
            }
            bv = __shfl_sync(0xffffffffu, bv, 0);
            bi = __shfl_sync(0xffffffffu, bi, 0);
            if (bi == tid)      v0 = -INFINITY;
            if (bi == tid + 32) v1 = -INFINITY;
            tv[r] = bv; tix[r] = bi;
        }
        if (tid == 0) {
            float m = tv[0], wv[TK], D = 0.f;
#pragma unroll
            for (int r = 0; r < TK; r++) { wv[r] = expf(tv[r] - m); D += wv[r]; }
            D = fmaxf(D, 1.1920929e-7f);
#pragma unroll
            for (int r = 0; r < TK; r++) { g_topw[s][r] = wv[r] / D; g_topi[s][r] = tix[r]; }
        }
    }
}

// ---------------- priority ----------------
__global__ void priority_kernel(const int* __restrict__ capacity) {
    int e = blockIdx.x, lane = threadIdx.x;
    int cap = capacity[0];
    if (cap > CAPMAX) cap = CAPMAX;
    if (cap < 0) cap = 0;

    int offset = 0;
    for (int base = 0; base < S_TOK * TK; base += 32) {
        int p = base + lane;
        int k = p / S_TOK;
        int s = p - k * S_TOK;
        bool match = (g_topi[s][k] == e);
        unsigned mask = __ballot_sync(0xffffffffu, match);
        if (match) {
            int c = offset + __popc(mask & ((1u << lane) - 1u));
            if (c < cap) { g_slot[s][k] = c; g_etok[e][c] = s; }
            else         { g_slot[s][k] = -1; }
        }
        offset += __popc(mask);
    }
    if (lane == 0) g_ecount[e] = (offset < cap) ? offset : cap;
}

// ---------------- GEMM1 (tf32 mma.sync, merged grid) + SwiGLU ----------------
// 1-D grid: blocks [0, 6144) = expert tiles (e = b/96, y = (b%96)/48, x = b%48),
//           blocks [6144, 6528) = shared tiles (y = b2/48, x = b2%48).
// Block: 128 rows x 64 output cols (pair: g1 + g2). 8 warps 2(M)x4(N).
__global__ __launch_bounds__(256, 2)
void gemm1_mma(const float* __restrict__ X,
               const float* __restrict__ Wsh,
               const float* __restrict__ Wex) {
    int b = blockIdx.x;
    int M, x, y; const int* gather; const float* Wp; float* Out;
    if (b < G1_EXP_BLKS) {
        int e   = b / 96;
        int rem = b - e * 96;
        y = rem / 48; x = rem - y * 48;
        M = g_ecount[e]; gather = g_etok[e];
        Wp = Wex + (size_t)e * I2 * HID; Out = &g_ex_gated[e][0][0];
    } else {
        int b2 = b - G1_EXP_BLKS;
        y = b2 / 48; x = b2 - y * 48;
        M = S_TOK; gather = nullptr; Wp = Wsh; Out = &g_sh_gated[0][0];
    }
    int m0 = y * BM;
    if (m0 >= M) return;
    int n0 = x * 64;

    uint32_t sb = smem_u32(dsm);
    int t = threadIdx.x, lane = t & 31, wid = t >> 5;
    int wm = wid >> 2, wn = wid & 3;     // 2 x 4 warp grid; warp = 64 rows x 16 cols
    int lq = lane >> 2, lr = lane & 3;

    int kseg = t & 7;
    int r32  = t >> 3;

    const float* ap[4];
#pragma unroll
    for (int p = 0; p < 4; p++) {
        int m = m0 + p * 32 + r32;
        ap[p] = (m < M) ? (X + (size_t)(gather ? gather[m] : m) * HID + kseg * 4) : nullptr;
    }
    const float* bp[4];
#pragma unroll
    for (int p = 0; p < 4; p++) {
        int row = p * 32 + r32;
        int wr = (row < 64) ? (n0 + row) : (n0 + row - 64 + I1);
        bp[p] = Wp + (size_t)wr * HID + kseg * 4;
    }

    float acc1[4][2][4], acc2[4][2][4];
#pragma unroll
    for (int mt = 0; mt < 4; mt++)
#pragma unroll
        for (int nt = 0; nt < 2; nt++)
#pragma unroll
            for (int i = 0; i < 4; i++) { acc1[mt][nt][i] = 0.f; acc2[mt][nt][i] = 0.f; }

    float4 va[4], vbr[4];
    uint32_t sts_off = (uint32_t)(r32 * PR + kseg * 4) * 4;

#pragma unroll
    for (int p = 0; p < 4; p++)
        va[p] = ap[p] ? *(const float4*)(ap[p]) : make_float4(0.f, 0.f, 0.f, 0.f);
#pragma unroll
    for (int p = 0; p < 4; p++) vbr[p] = *(const float4*)(bp[p]);
    {
        uint32_t Ab = sb, Bb = sb + A_BYTES;
#pragma unroll
        for (int p = 0; p < 4; p++) cvt_sts(Ab + p * 32 * PR * 4 + sts_off, va[p]);
#pragma unroll
        for (int p = 0; p < 4; p++) cvt_sts(Bb + p * 32 * PR * 4 + sts_off, vbr[p]);
    }
    __syncthreads();

#pragma unroll 1
    for (int kc = 0; kc < NC1; kc++) {
        int buf = kc & 1;
        if (kc + 1 < NC1) {
            int ko = (kc + 1) * BK;
#pragma unroll
            for (int p = 0; p < 4; p++)
                va[p] = ap[p] ? *(const float4*)(ap[p] + ko) : make_float4(0.f, 0.f, 0.f, 0.f);
#pragma unroll
            for (int p = 0; p < 4; p++) vbr[p] = *(const float4*)(bp[p] + ko);
        }
        uint32_t Ab = sb + buf * STG;
        uint32_t Bb = Ab + A_BYTES;
#pragma unroll
        for (int ks = 0; ks < 4; ks++) {
            uint32_t kcol = (uint32_t)(ks * 8 + lr) * 4;
            uint32_t b1v[2][2], b2v[2][2];
#pragma unroll
            for (int nt = 0; nt < 2; nt++) {
                uint32_t base1 = Bb + (uint32_t)((wn * 16 + nt * 8 + lq) * PR) * 4 + kcol;
                b1v[nt][0] = lds_u32(base1);
                b1v[nt][1] = lds_u32(base1 + 16);
                uint32_t base2 = base1 + 64 * PR * 4;
                b2v[nt][0] = lds_u32(base2);
                b2v[nt][1] = lds_u32(base2 + 16);
            }
#pragma unroll
            for (int mt = 0; mt < 4; mt++) {
                uint32_t a[4];
                uint32_t base = Ab + (uint32_t)((wm * 64 + mt * 16 + lq) * PR) * 4 + kcol;
                a[0] = lds_u32(base);
                a[1] = lds_u32(base + 8 * PR * 4);
                a[2] = lds_u32(base + 16);
                a[3] = lds_u32(base + 8 * PR * 4 + 16);
#pragma unroll
                for (int nt = 0; nt < 2; nt++) {
                    MMA_TF32(acc1[mt][nt], a, b1v[nt][0], b1v[nt][1]);
                    MMA_TF32(acc2[mt][nt], a, b2v[nt][0], b2v[nt][1]);
                }
            }
        }
        if (kc + 1 < NC1) {
            uint32_t Ab2 = sb + (buf ^ 1) * STG;
            uint32_t Bb2 = Ab2 + A_BYTES;
#pragma unroll
            for (int p = 0; p < 4; p++) cvt_sts(Ab2 + p * 32 * PR * 4 + sts_off, va[p]);
#pragma unroll
            for (int p = 0; p < 4; p++) cvt_sts(Bb2 + p * 32 * PR * 4 + sts_off, vbr[p]);
        }
        __syncthreads();
    }

    // epilogue: fused SwiGLU; outputs pre-rounded to tf32 (gemm2 consumes raw)
#pragma unroll
    for (int mt = 0; mt < 4; mt++) {
        int rbase = m0 + wm * 64 + mt * 16 + lq;
#pragma unroll
        for (int nt = 0; nt < 2; nt++) {
            int col = n0 + wn * 16 + nt * 8 + lr * 2;
#pragma unroll
            for (int half = 0; half < 2; half++) {
                int r = rbase + half * 8;
                if (r < M) {
                    float g1a = acc1[mt][nt][half * 2 + 0];
                    float g1b = acc1[mt][nt][half * 2 + 1];
                    float g2a = acc2[mt][nt][half * 2 + 0];
                    float g2b = acc2[mt][nt][half * 2 + 1];
                    float2 o;
                    o.x = tf32r(g1a * (g2a / (1.f + expf(-g2a))));
                    o.y = tf32r(g1b * (g2b / (1.f + expf(-g2b))));
                    *(float2*)&Out[(size_t)r * I1 + col] = o;
                }
            }
        }
    }
}

// ---------------- GEMM2 (tf32 mma.sync, merged grid): 128 x 128 tile ----------------
// blocks [0,768) expert (e = b/12, y = (b%12)/6, x = b%6); [768,816) shared.
__global__ __launch_bounds__(256, 2)
void gemm2_mma(const float* __restrict__ Wsh,
               const float* __restrict__ Wex,
               float* __restrict__ dout) {
    int b = blockIdx.x;
    int M, x, y; const float* G; const float* Wp; float* Out;
    if (b < G2_EXP_BLKS) {
        int e   = b / 12;
        int rem = b - e * 12;
        y = rem / 6; x = rem - y * 6;
        M = g_ecount[e]; G = &g_ex_gated[e][0][0];
        Wp = Wex + (size_t)e * HID * I1; Out = &g_ex_out[e][0][0];
    } else {
        int b2 = b - G2_EXP_BLKS;
        y = b2 / 6; x = b2 - y * 6;
        M = S_TOK; G = &g_sh_gated[0][0]; Wp = Wsh; Out = dout;
    }
    int m0 = y * BM;
    if (m0 >= M) return;
    int n0 = x * 128;

    uint32_t sb = smem_u32(dsm);
    int t = threadIdx.x, lane = t & 31, wid = t >> 5;
    int wm = wid >> 2, wn = wid & 3;     // warp = 64 rows x 32 cols
    int lq = lane >> 2, lr = lane & 3;

    int kseg = t & 7;
    int r32  = t >> 3;

    const float* ap[4];
#pragma unroll
    for (int p = 0; p < 4; p++) {
        int m = m0 + p * 32 + r32;
        ap[p] = (m < M) ? (G + (size_t)m * I1 + kseg * 4) : nullptr;
    }
    const float* bp[4];
#pragma unroll
    for (int p = 0; p < 4; p++)
        bp[p] = Wp + (size_t)(n0 + p * 32 + r32) * I1 + kseg * 4;

    float acc[4][4][4];
#pragma unroll
    for (int mt = 0; mt < 4; mt++)
#pragma unroll
        for (int nt = 0; nt < 4; nt++)
#pragma unroll
            for (int i = 0; i < 4; i++) acc[mt][nt][i] = 0.f;

    float4 va[4], vbr[4];
    uint32_t sts_off = (uint32_t)(r32 * PR + kseg * 4) * 4;

#pragma unroll
    for (int p = 0; p < 4; p++)
        va[p] = ap[p] ? *(const float4*)(ap[p]) : make_float4(0.f, 0.f, 0.f, 0.f);
#pragma unroll
    for (int p = 0; p < 4; p++) vbr[p] = *(const float4*)(bp[p]);
    {
        uint32_t Ab = sb, Bb = sb + A_BYTES;
#pragma unroll
        for (int p = 0; p < 4; p++) raw_sts(Ab + p * 32 * PR * 4 + sts_off, va[p]);
#pragma unroll
        for (int p = 0; p < 4; p++) cvt_sts(Bb + p * 32 * PR * 4 + sts_off, vbr[p]);
    }
    __syncthreads();

#pragma unroll 1
    for (int kc = 0; kc < NC2; kc++) {
        int buf = kc & 1;
        if (kc + 1 < NC2) {
            int ko = (kc + 1) * BK;
#pragma unroll
            for (int p = 0; p < 4; p++)
                va[p] = ap[p] ? *(const float4*)(ap[p] + ko) : make_float4(0.f, 0.f, 0.f, 0.f);
#pragma unroll
            for (int p = 0; p < 4; p++) vbr[p] = *(const float4*)(bp[p] + ko);
        }
        uint32_t Ab = sb + buf * STG;
        uint32_t Bb = Ab + A_BYTES;
#pragma unroll
        for (int ks = 0; ks < 4; ks++) {
            uint32_t kcol = (uint32_t)(ks * 8 + lr) * 4;
            uint32_t bv[4][2];
#pragma unroll
            for (int nt = 0; nt < 4; nt++) {
                uint32_t base = Bb + (uint32_t)((wn * 32 + nt * 8 + lq) * PR) * 4 + kcol;
                bv[nt][0] = lds_u32(base);
                bv[nt][1] = lds_u32(base + 16);
            }
#pragma unroll
            for (int mt = 0; mt < 4; mt++) {
                uint32_t a[4];
                uint32_t base = Ab + (uint32_t)((wm * 64 + mt * 16 + lq) * PR) * 4 + kcol;
                a[0] = lds_u32(base);
                a[1] = lds_u32(base + 8 * PR * 4);
                a[2] = lds_u32(base + 16);
                a[3] = lds_u32(base + 8 * PR * 4 + 16);
#pragma unroll
                for (int nt = 0; nt < 4; nt++)
                    MMA_TF32(acc[mt][nt], a, bv[nt][0], bv[nt][1]);
            }
        }
        if (kc + 1 < NC2) {
            uint32_t Ab2 = sb + (buf ^ 1) * STG;
            uint32_t Bb2 = Ab2 + A_BYTES;
#pragma unroll
            for (int p = 0; p < 4; p++) raw_sts(Ab2 + p * 32 * PR * 4 + sts_off, va[p]);
#pragma unroll
            for (int p = 0; p < 4; p++) cvt_sts(Bb2 + p * 32 * PR * 4 + sts_off, vbr[p]);
        }
        __syncthreads();
    }

#pragma unroll
    for (int mt = 0; mt < 4; mt++) {
        int rbase = m0 + wm * 64 + mt * 16 + lq;
#pragma unroll
        for (int nt = 0; nt < 4; nt++) {
            int col = n0 + wn * 32 + nt * 8 + lr * 2;
#pragma unroll
            for (int half = 0; half < 2; half++) {
                int r = rbase + half * 8;
                if (r < M) {
                    float2 o;
                    o.x = acc[mt][nt][half * 2 + 0];
                    o.y = acc[mt][nt][half * 2 + 1];
                    *(float2*)&Out[(size_t)r * HID + col] = o;
                }
            }
        }
    }
}

// ---------------- combine ----------------
__global__ void combine_kernel(float* __restrict__ out) {
    int s = blockIdx.x, tid = threadIdx.x;
    __shared__ int ke[TK], kc_[TK];
    __shared__ float kw[TK];
    if (tid < TK) { ke[tid] = g_topi[s][tid]; kc_[tid] = g_slot[s][tid]; kw[tid] = g_topw[s][tid]; }
    __syncthreads();
    for (int h = tid; h < HID; h += 256) {
        float acc = out[(size_t)s * HID + h];
#pragma unroll
        for (int k = 0; k < TK; k++) {
            int c = kc_[k];
            if (c >= 0) acc += kw[k] * g_ex_out[ke[k]][c][h];
        }
        out[(size_t)s * HID + h] = acc;
    }
}

// ---------------------------------------------------------------------------
extern "C" void kernel_launch(void* const* d_in, const int* in_sizes, int n_in,
                              void* d_out, int out_size) {
    const float* x      = (const float*)d_in[0];
    const float* w_gu   = (const float*)d_in[1];
    const float* w_down = (const float*)d_in[2];
    const float* wg     = (const float*)d_in[3];
    const float* w1     = (const float*)d_in[4];
    const float* w2     = (const float*)d_in[5];
    const int*   cap    = (const int*)d_in[6];
    float* out = (float*)d_out;

    cudaFuncSetAttribute(gemm1_mma, cudaFuncAttributeMaxDynamicSharedMemorySize, SMEM_BYTES);
    cudaFuncSetAttribute(gemm2_mma, cudaFuncAttributeMaxDynamicSharedMemorySize, SMEM_BYTES);

    gating_kernel<<<S_TOK, 256>>>(x, wg);
    priority_kernel<<<NE, 32>>>(cap);

    gemm1_mma<<<G1_EXP_BLKS + G1_SH_BLKS, 256, SMEM_BYTES>>>(x, w_gu, w1);
    gemm2_mma<<<G2_EXP_BLKS + G2_SH_BLKS, 256, SMEM_BYTES>>>(w_down, w2, out);

    combine_kernel<<<S_TOK, 256>>>(out);
}

// round 8
// speedup vs baseline: 1.4225x; 1.0113x over previous
#include <cuda_runtime.h>
#include <cstdint>
#include <math.h>

// ---------------- problem constants ----------------
#define S_TOK   1024
#define HID     768
#define NE      64
#define TK      8
#define CAPMAX  256
#define I1      3072
#define I2      6144

// ---------------- GEMM tiling ----------------
#define BM   128
#define BK   32
#define PR   36                        // padded row length (floats)
#define A_BYTES (BM * PR * 4)          // 18432
#define B_BYTES (128 * PR * 4)         // 18432
#define STG     (A_BYTES + B_BYTES)    // 36864
#define SMEM_BYTES (2 * STG)           // 73728
#define NC1 (HID / BK)                 // 24
#define NC2 (I1 / BK)                  // 96

// merged-grid sizes
#define G1_EXP_BLKS (48 * 2 * NE)      // 6144
#define G1_SH_BLKS  (48 * 8)           // 384
#define G2_EXP_BLKS (6 * 2 * NE)       // 768
#define G2_SH_BLKS  (6 * 8)            // 48

// ---------------- device scratch ----------------
__device__ __align__(16)  float g_topw[S_TOK][TK];
__device__ __align__(16)  int   g_topi[S_TOK][TK];
__device__ __align__(16)  int   g_slot[S_TOK][TK];
__device__ __align__(16)  int   g_ecount[NE];
__device__ __align__(16)  int   g_etok[NE][CAPMAX];
__device__ __align__(256) float g_sh_gated[S_TOK][I1];
__device__ __align__(256) float g_ex_gated[NE][CAPMAX][I1];
__device__ __align__(256) float g_ex_out[NE][CAPMAX][HID];

// ---------------- helpers ----------------
__device__ __forceinline__ uint32_t smem_u32(const void* p) {
    uint32_t a;
    asm("{ .reg .u64 t; cvta.to.shared.u64 t, %1; cvt.u32.u64 %0, t; }" : "=r"(a) : "l"(p));
    return a;
}
__device__ __forceinline__ uint32_t lds_u32(uint32_t addr) {
    uint32_t v;
    asm volatile("ld.shared.b32 %0, [%1];" : "=r"(v) : "r"(addr));
    return v;
}
// convert 4 fp32 -> tf32 (RNA) and store 16B to smem
__device__ __forceinline__ void cvt_sts(uint32_t addr, float4 v) {
    uint32_t a, b, c, d;
    asm volatile("cvt.rna.tf32.f32 %0, %1;" : "=r"(a) : "f"(v.x));
    asm volatile("cvt.rna.tf32.f32 %0, %1;" : "=r"(b) : "f"(v.y));
    asm volatile("cvt.rna.tf32.f32 %0, %1;" : "=r"(c) : "f"(v.z));
    asm volatile("cvt.rna.tf32.f32 %0, %1;" : "=r"(d) : "f"(v.w));
    asm volatile("st.shared.v4.b32 [%0], {%1, %2, %3, %4};"
                 :: "r"(addr), "r"(a), "r"(b), "r"(c), "r"(d) : "memory");
}
// raw store (data already tf32-rounded)
__device__ __forceinline__ void raw_sts(uint32_t addr, float4 v) {
    asm volatile("st.shared.v4.b32 [%0], {%1, %2, %3, %4};"
                 :: "r"(addr), "r"(__float_as_uint(v.x)), "r"(__float_as_uint(v.y)),
                    "r"(__float_as_uint(v.z)), "r"(__float_as_uint(v.w)) : "memory");
}
__device__ __forceinline__ float tf32r(float x) {
    uint32_t v;
    asm("cvt.rna.tf32.f32 %0, %1;" : "=r"(v) : "f"(x));
    return __uint_as_float(v);
}
#define MMA_TF32(c, a, b0v, b1v) \
    asm volatile("mma.sync.aligned.m16n8k8.row.col.f32.tf32.tf32.f32 " \
        "{%0,%1,%2,%3}, {%4,%5,%6,%7}, {%8,%9}, {%0,%1,%2,%3};" \
        : "+f"((c)[0]), "+f"((c)[1]), "+f"((c)[2]), "+f"((c)[3]) \
        : "r"((a)[0]), "r"((a)[1]), "r"((a)[2]), "r"((a)[3]), "r"(b0v), "r"(b1v))

extern __shared__ char dsm[];

// ---------------- gating ----------------
__global__ void gating_kernel(const float* __restrict__ x,
                              const float* __restrict__ wg) {
    int s = blockIdx.x;
    __shared__ float xs[HID];
    __shared__ float logits_s[NE];
    int tid = threadIdx.x;

    for (int i = tid; i < HID; i += 256) xs[i] = x[(size_t)s * HID + i];
    __syncthreads();

    int e = tid >> 2, sub = tid & 3;
    const float* w = wg + (size_t)e * HID;
    float acc = 0.f;
    for (int i = sub; i < HID; i += 4) acc += xs[i] * w[i];
    acc += __shfl_down_sync(0xffffffffu, acc, 2);
    acc += __shfl_down_sync(0xffffffffu, acc, 1);
    if (sub == 0) logits_s[e] = acc;
    __syncthreads();

    if (tid < 32) {
        float v0 = logits_s[tid];
        float v1 = logits_s[tid + 32];
        float tv[TK]; int tix[TK];
#pragma unroll
        for (int r = 0; r < TK; r++) {
            float bv; int bi;
            if (v0 >= v1) { bv = v0; bi = tid; }
            else          { bv = v1; bi = tid + 32; }
#pragma unroll
            for (int off = 16; off > 0; off >>= 1) {
                float ov = __shfl_down_sync(0xffffffffu, bv, off);
                int   oi = __shfl_down_sync(0xffffffffu, bi, off);
                if (ov > bv || (ov == bv && oi < bi)) { bv = ov; bi = oi; }
            }
            bv = __shfl_sync(0xffffffffu, bv, 0);
            bi = __shfl_sync(0xffffffffu, bi, 0);
            if (bi == tid)      v0 = -INFINITY;
            if (bi == tid + 32) v1 = -INFINITY;
            tv[r] = bv; tix[r] = bi;
        }
        if (tid == 0) {
            float m = tv[0], wv[TK], D = 0.f;
#pragma unroll
            for (int r = 0; r < TK; r++) { wv[r] = expf(tv[r] - m); D += wv[r]; }
            D = fmaxf(D, 1.1920929e-7f);
#pragma unroll
            for (int r = 0; r < TK; r++) { g_topw[s][r] = wv[r] / D; g_topi[s][r] = tix[r]; }
        }
    }
}

// ---------------- priority ----------------
__global__ void priority_kernel(const int* __restrict__ capacity) {
    int e = blockIdx.x, lane = threadIdx.x;
    int cap = capacity[0];
    if (cap > CAPMAX) cap = CAPMAX;
    if (cap < 0) cap = 0;

    int offset = 0;
    for (int base = 0; base < S_TOK * TK; base += 32) {
        int p = base + lane;
        int k = p / S_TOK;
        int s = p - k * S_TOK;
        bool match = (g_topi[s][k] == e);
        unsigned mask = __ballot_sync(0xffffffffu, match);
        if (match) {
            int c = offset + __popc(mask & ((1u << lane) - 1u));
            if (c < cap) { g_slot[s][k] = c; g_etok[e][c] = s; }
            else         { g_slot[s][k] = -1; }
        }
        offset += __popc(mask);
    }
    if (lane == 0) g_ecount[e] = (offset < cap) ? offset : cap;
}

// ---------------- GEMM1 (tf32 mma.sync, merged grid, interleaved rows) + SwiGLU ----
// Row map: warp wm's tile mt covers local rows (mt*2+wm)*16 .. +16.
// ntiles = ceil(Mrem/16); warps share partial tiles evenly.
__global__ __launch_bounds__(256, 2)
void gemm1_mma(const float* __restrict__ X,
               const float* __restrict__ Wsh,
               const float* __restrict__ Wex) {
    int b = blockIdx.x;
    int M, x, y; const int* gather; const float* Wp; float* Out;
    if (b < G1_EXP_BLKS) {
        int e   = b / 96;
        int rem = b - e * 96;
        y = rem / 48; x = rem - y * 48;
        M = g_ecount[e]; gather = g_etok[e];
        Wp = Wex + (size_t)e * I2 * HID; Out = &g_ex_gated[e][0][0];
    } else {
        int b2 = b - G1_EXP_BLKS;
        y = b2 / 48; x = b2 - y * 48;
        M = S_TOK; gather = nullptr; Wp = Wsh; Out = &g_sh_gated[0][0];
    }
    int m0 = y * BM;
    if (m0 >= M) return;
    int n0 = x * 64;
    int Mrem = M - m0; if (Mrem > BM) Mrem = BM;
    int ntiles = (Mrem + 15) >> 4;     // 1..8
    int npass  = (ntiles + 1) >> 1;    // 32-row loader passes

    uint32_t sb = smem_u32(dsm);
    int t = threadIdx.x, lane = t & 31, wid = t >> 5;
    int wm = wid >> 2, wn = wid & 3;   // 2 x 4 warp grid
    int lq = lane >> 2, lr = lane & 3;

    int kseg = t & 7;
    int r32  = t >> 3;

    const float* ap[4];
#pragma unroll
    for (int p = 0; p < 4; p++) {
        int m = m0 + p * 32 + r32;
        ap[p] = (p < npass && m < M) ? (X + (size_t)(gather ? gather[m] : m) * HID + kseg * 4) : nullptr;
    }
    const float* bp[4];
#pragma unroll
    for (int p = 0; p < 4; p++) {
        int row = p * 32 + r32;
        int wr = (row < 64) ? (n0 + row) : (n0 + row - 64 + I1);
        bp[p] = Wp + (size_t)wr * HID + kseg * 4;
    }

    float acc1[4][2][4], acc2[4][2][4];
#pragma unroll
    for (int mt = 0; mt < 4; mt++)
#pragma unroll
        for (int nt = 0; nt < 2; nt++)
#pragma unroll
            for (int i = 0; i < 4; i++) { acc1[mt][nt][i] = 0.f; acc2[mt][nt][i] = 0.f; }

    float4 va[4], vbr[4];
    uint32_t sts_off = (uint32_t)(r32 * PR + kseg * 4) * 4;

#pragma unroll
    for (int p = 0; p < 4; p++)
        va[p] = ap[p] ? *(const float4*)(ap[p]) : make_float4(0.f, 0.f, 0.f, 0.f);
#pragma unroll
    for (int p = 0; p < 4; p++) vbr[p] = *(const float4*)(bp[p]);
    {
        uint32_t Ab = sb, Bb = sb + A_BYTES;
#pragma unroll
        for (int p = 0; p < 4; p++) if (p < npass) cvt_sts(Ab + p * 32 * PR * 4 + sts_off, va[p]);
#pragma unroll
        for (int p = 0; p < 4; p++) cvt_sts(Bb + p * 32 * PR * 4 + sts_off, vbr[p]);
    }
    __syncthreads();

#pragma unroll 1
    for (int kc = 0; kc < NC1; kc++) {
        int buf = kc & 1;
        if (kc + 1 < NC1) {
            int ko = (kc + 1) * BK;
#pragma unroll
            for (int p = 0; p < 4; p++)
                va[p] = ap[p] ? *(const float4*)(ap[p] + ko) : make_float4(0.f, 0.f, 0.f, 0.f);
#pragma unroll
            for (int p = 0; p < 4; p++) vbr[p] = *(const float4*)(bp[p] + ko);
        }
        uint32_t Ab = sb + buf * STG;
        uint32_t Bb = Ab + A_BYTES;
#pragma unroll
        for (int ks = 0; ks < 4; ks++) {
            uint32_t kcol = (uint32_t)(ks * 8 + lr) * 4;
            uint32_t b1v[2][2], b2v[2][2];
#pragma unroll
            for (int nt = 0; nt < 2; nt++) {
                uint32_t base1 = Bb + (uint32_t)((wn * 16 + nt * 8 + lq) * PR) * 4 + kcol;
                b1v[nt][0] = lds_u32(base1);
                b1v[nt][1] = lds_u32(base1 + 16);
                uint32_t base2 = base1 + 64 * PR * 4;
                b2v[nt][0] = lds_u32(base2);
                b2v[nt][1] = lds_u32(base2 + 16);
            }
#pragma unroll
            for (int mt = 0; mt < 4; mt++) {
                int ti = mt * 2 + wm;
                if (ti < ntiles) {
                    uint32_t a[4];
                    uint32_t base = Ab + (uint32_t)((ti * 16 + lq) * PR) * 4 + kcol;
                    a[0] = lds_u32(base);
                    a[1] = lds_u32(base + 8 * PR * 4);
                    a[2] = lds_u32(base + 16);
                    a[3] = lds_u32(base + 8 * PR * 4 + 16);
#pragma unroll
                    for (int nt = 0; nt < 2; nt++) {
                        MMA_TF32(acc1[mt][nt], a, b1v[nt][0], b1v[nt][1]);
                        MMA_TF32(acc2[mt][nt], a, b2v[nt][0], b2v[nt][1]);
                    }
                }
            }
        }
        if (kc + 1 < NC1) {
            uint32_t Ab2 = sb + (buf ^ 1) * STG;
            uint32_t Bb2 = Ab2 + A_BYTES;
#pragma unroll
            for (int p = 0; p < 4; p++) if (p < npass) cvt_sts(Ab2 + p * 32 * PR * 4 + sts_off, va[p]);
#pragma unroll
            for (int p = 0; p < 4; p++) cvt_sts(Bb2 + p * 32 * PR * 4 + sts_off, vbr[p]);
        }
        __syncthreads();
    }

    // epilogue: fused SwiGLU; outputs pre-rounded to tf32 (gemm2 consumes raw)
#pragma unroll
    for (int mt = 0; mt < 4; mt++) {
        int ti = mt * 2 + wm;
        if (ti >= ntiles) continue;
        int rbase = m0 + ti * 16 + lq;
#pragma unroll
        for (int nt = 0; nt < 2; nt++) {
            int col = n0 + wn * 16 + nt * 8 + lr * 2;
#pragma unroll
            for (int half = 0; half < 2; half++) {
                int r = rbase + half * 8;
                if (r < M) {
                    float g1a = acc1[mt][nt][half * 2 + 0];
                    float g1b = acc1[mt][nt][half * 2 + 1];
                    float g2a = acc2[mt][nt][half * 2 + 0];
                    float g2b = acc2[mt][nt][half * 2 + 1];
                    float2 o;
                    o.x = tf32r(g1a * (g2a / (1.f + expf(-g2a))));
                    o.y = tf32r(g1b * (g2b / (1.f + expf(-g2b))));
                    *(float2*)&Out[(size_t)r * I1 + col] = o;
                }
            }
        }
    }
}

// ---------------- GEMM2 (tf32 mma.sync, merged grid, interleaved rows) --------------
__global__ __launch_bounds__(256, 2)
void gemm2_mma(const float* __restrict__ Wsh,
               const float* __restrict__ Wex,
               float* __restrict__ dout) {
    int b = blockIdx.x;
    int M, x, y; const float* G; const float* Wp; float* Out;
    if (b < G2_EXP_BLKS) {
        int e   = b / 12;
        int rem = b - e * 12;
        y = rem / 6; x = rem - y * 6;
        M = g_ecount[e]; G = &g_ex_gated[e][0][0];
        Wp = Wex + (size_t)e * HID * I1; Out = &g_ex_out[e][0][0];
    } else {
        int b2 = b - G2_EXP_BLKS;
        y = b2 / 6; x = b2 - y * 6;
        M = S_TOK; G = &g_sh_gated[0][0]; Wp = Wsh; Out = dout;
    }
    int m0 = y * BM;
    if (m0 >= M) return;
    int n0 = x * 128;
    int Mrem = M - m0; if (Mrem > BM) Mrem = BM;
    int ntiles = (Mrem + 15) >> 4;
    int npass  = (ntiles + 1) >> 1;

    uint32_t sb = smem_u32(dsm);
    int t = threadIdx.x, lane = t & 31, wid = t >> 5;
    int wm = wid >> 2, wn = wid & 3;
    int lq = lane >> 2, lr = lane & 3;

    int kseg = t & 7;
    int r32  = t >> 3;

    const float* ap[4];
#pragma unroll
    for (int p = 0; p < 4; p++) {
        int m = m0 + p * 32 + r32;
        ap[p] = (p < npass && m < M) ? (G + (size_t)m * I1 + kseg * 4) : nullptr;
    }
    const float* bp[4];
#pragma unroll
    for (int p = 0; p < 4; p++)
        bp[p] = Wp + (size_t)(n0 + p * 32 + r32) * I1 + kseg * 4;

    float acc[4][4][4];
#pragma unroll
    for (int mt = 0; mt < 4; mt++)
#pragma unroll
        for (int nt = 0; nt < 4; nt++)
#pragma unroll
            for (int i = 0; i < 4; i++) acc[mt][nt][i] = 0.f;

    float4 va[4], vbr[4];
    uint32_t sts_off = (uint32_t)(r32 * PR + kseg * 4) * 4;

#pragma unroll
    for (int p = 0; p < 4; p++)
        va[p] = ap[p] ? *(const float4*)(ap[p]) : make_float4(0.f, 0.f, 0.f, 0.f);
#pragma unroll
    for (int p = 0; p < 4; p++) vbr[p] = *(const float4*)(bp[p]);
    {
        uint32_t Ab = sb, Bb = sb + A_BYTES;
#pragma unroll
        for (int p = 0; p < 4; p++) if (p < npass) raw_sts(Ab + p * 32 * PR * 4 + sts_off, va[p]);
#pragma unroll
        for (int p = 0; p < 4; p++) cvt_sts(Bb + p * 32 * PR * 4 + sts_off, vbr[p]);
    }
    __syncthreads();

#pragma unroll 1
    for (int kc = 0; kc < NC2; kc++) {
        int buf = kc & 1;
        if (kc + 1 < NC2) {
            int ko = (kc + 1) * BK;
#pragma unroll
            for (int p = 0; p < 4; p++)
                va[p] = ap[p] ? *(const float4*)(ap[p] + ko) : make_float4(0.f, 0.f, 0.f, 0.f);
#pragma unroll
            for (int p = 0; p < 4; p++) vbr[p] = *(const float4*)(bp[p] + ko);
        }
        uint32_t Ab = sb + buf * STG;
        uint32_t Bb = Ab + A_BYTES;
#pragma unroll
        for (int ks = 0; ks < 4; ks++) {
            uint32_t kcol = (uint32_t)(ks * 8 + lr) * 4;
            uint32_t bv[4][2];
#pragma unroll
            for (int nt = 0; nt < 4; nt++) {
                uint32_t base = Bb + (uint32_t)((wn * 32 + nt * 8 + lq) * PR) * 4 + kcol;
                bv[nt][0] = lds_u32(base);
                bv[nt][1] = lds_u32(base + 16);
            }
#pragma unroll
            for (int mt = 0; mt < 4; mt++) {
                int ti = mt * 2 + wm;
                if (ti < ntiles) {
                    uint32_t a[4];
                    uint32_t base = Ab + (uint32_t)((ti * 16 + lq) * PR) * 4 + kcol;
                    a[0] = lds_u32(base);
                    a[1] = lds_u32(base + 8 * PR * 4);
                    a[2] = lds_u32(base + 16);
                    a[3] = lds_u32(base + 8 * PR * 4 + 16);
#pragma unroll
                    for (int nt = 0; nt < 4; nt++)
                        MMA_TF32(acc[mt][nt], a, bv[nt][0], bv[nt][1]);
                }
            }
        }
        if (kc + 1 < NC2) {
            uint32_t Ab2 = sb + (buf ^ 1) * STG;
            uint32_t Bb2 = Ab2 + A_BYTES;
#pragma unroll
            for (int p = 0; p < 4; p++) if (p < npass) raw_sts(Ab2 + p * 32 * PR * 4 + sts_off, va[p]);
#pragma unroll
            for (int p = 0; p < 4; p++) cvt_sts(Bb2 + p * 32 * PR * 4 + sts_off, vbr[p]);
        }
        __syncthreads();
    }

#pragma unroll
    for (int mt = 0; mt < 4; mt++) {
        int ti = mt * 2 + wm;
        if (ti >= ntiles) continue;
        int rbase = m0 + ti * 16 + lq;
#pragma unroll
        for (int nt = 0; nt < 4; nt++) {
            int col = n0 + wn * 32 + nt * 8 + lr * 2;
#pragma unroll
            for (int half = 0; half < 2; half++) {
                int r = rbase + half * 8;
                if (r < M) {
                    float2 o;
                    o.x = acc[mt][nt][half * 2 + 0];
                    o.y = acc[mt][nt][half * 2 + 1];
                    *(float2*)&Out[(size_t)r * HID + col] = o;
                }
            }
        }
    }
}

// ---------------- combine ----------------
__global__ void combine_kernel(float* __restrict__ out) {
    int s = blockIdx.x, tid = threadIdx.x;
    __shared__ int ke[TK], kc_[TK];
    __shared__ float kw[TK];
    if (tid < TK) { ke[tid] = g_topi[s][tid]; kc_[tid] = g_slot[s][tid]; kw[tid] = g_topw[s][tid]; }
    __syncthreads();
    for (int h = tid; h < HID; h += 256) {
        float acc = out[(size_t)s * HID + h];
#pragma unroll
        for (int k = 0; k < TK; k++) {
            int c = kc_[k];
            if (c >= 0) acc += kw[k] * g_ex_out[ke[k]][c][h];
        }
        out[(size_t)s * HID + h] = acc;
    }
}

// ---------------------------------------------------------------------------
extern "C" void kernel_launch(void* const* d_in, const int* in_sizes, int n_in,
                              void* d_out, int out_size) {
    const float* x      = (const float*)d_in[0];
    const float* w_gu   = (const float*)d_in[1];
    const float* w_down = (const float*)d_in[2];
    const float* wg     = (const float*)d_in[3];
    const float* w1     = (const float*)d_in[4];
    const float* w2     = (const float*)d_in[5];
    const int*   cap    = (const int*)d_in[6];
    float* out = (float*)d_out;

    cudaFuncSetAttribute(gemm1_mma, cudaFuncAttributeMaxDynamicSharedMemorySize, SMEM_BYTES);
    cudaFuncSetAttribute(gemm2_mma, cudaFuncAttributeMaxDynamicSharedMemorySize, SMEM_BYTES);

    gating_kernel<<<S_TOK, 256>>>(x, wg);
    priority_kernel<<<NE, 32>>>(cap);

    gemm1_mma<<<G1_EXP_BLKS + G1_SH_BLKS, 256, SMEM_BYTES>>>(x, w_gu, w1);
    gemm2_mma<<<G2_EXP_BLKS + G2_SH_BLKS, 256, SMEM_BYTES>>>(w_down, w2, out);

    combine_kernel<<<S_TOK, 256>>>(out);
}

// round 9
// speedup vs baseline: 1.5219x; 1.0698x over previous
#include <cuda_runtime.h>
#include <cstdint>
#include <math.h>

// ---------------- problem constants ----------------
#define S_TOK   1024
#define HID     768
#define NE      64
#define TK      8
#define CAPMAX  256
#define I1      3072
#define I2      6144

// ---------------- GEMM tiling ----------------
#define BM   128
#define BK   32
#define PR   36                        // padded row length (floats)
#define A_BYTES (BM * PR * 4)          // 18432
#define B_BYTES (128 * PR * 4)         // 18432
#define STG     (A_BYTES + B_BYTES)    // 36864
#define SMEM_BYTES (2 * STG)           // 73728
#define NC1 (HID / BK)                 // 24
#define NC2 (I1 / BK)                  // 96

// merged-grid sizes
#define G1_EXP_BLKS (48 * 2 * NE)      // 6144
#define G1_SH_BLKS  (48 * 8)           // 384
#define G2_EXP_BLKS (6 * 2 * NE)       // 768
#define G2_SH_BLKS  (6 * 8)            // 48

// ---------------- device scratch ----------------
__device__ __align__(16)  float g_topw[S_TOK][TK];
__device__ __align__(16)  int   g_topi[S_TOK][TK];
__device__ __align__(16)  int   g_slot[S_TOK][TK];
__device__ __align__(16)  int   g_ecount[NE];
__device__ __align__(16)  int   g_etok[NE][CAPMAX];
__device__ __align__(256) float g_xr[S_TOK][HID];             // tf32-rounded X
__device__ __align__(256) float g_sh_gated[S_TOK][I1];
__device__ __align__(256) float g_ex_gated[NE][CAPMAX][I1];
__device__ __align__(256) float g_ex_out[NE][CAPMAX][HID];

// ---------------- helpers ----------------
__device__ __forceinline__ uint32_t smem_u32(const void* p) {
    uint32_t a;
    asm("{ .reg .u64 t; cvta.to.shared.u64 t, %1; cvt.u32.u64 %0, t; }" : "=r"(a) : "l"(p));
    return a;
}
__device__ __forceinline__ uint32_t lds_u32(uint32_t addr) {
    uint32_t v;
    asm volatile("ld.shared.b32 %0, [%1];" : "=r"(v) : "r"(addr));
    return v;
}
// convert 4 fp32 -> tf32 (RNA) and store 16B to smem
__device__ __forceinline__ void cvt_sts(uint32_t addr, float4 v) {
    uint32_t a, b, c, d;
    asm volatile("cvt.rna.tf32.f32 %0, %1;" : "=r"(a) : "f"(v.x));
    asm volatile("cvt.rna.tf32.f32 %0, %1;" : "=r"(b) : "f"(v.y));
    asm volatile("cvt.rna.tf32.f32 %0, %1;" : "=r"(c) : "f"(v.z));
    asm volatile("cvt.rna.tf32.f32 %0, %1;" : "=r"(d) : "f"(v.w));
    asm volatile("st.shared.v4.b32 [%0], {%1, %2, %3, %4};"
                 :: "r"(addr), "r"(a), "r"(b), "r"(c), "r"(d) : "memory");
}
__device__ __forceinline__ float tf32r(float x) {
    uint32_t v;
    asm("cvt.rna.tf32.f32 %0, %1;" : "=r"(v) : "f"(x));
    return __uint_as_float(v);
}
// async 16B copy gmem->smem; pred=0 zero-fills (no src read)
__device__ __forceinline__ void cpa16(uint32_t dst, const float* src, int pred) {
    int sz = pred ? 16 : 0;
    asm volatile("cp.async.cg.shared.global [%0], [%1], 16, %2;"
                 :: "r"(dst), "l"(src), "r"(sz) : "memory");
}
#define CP_COMMIT() asm volatile("cp.async.commit_group;" ::: "memory")
#define CP_WAIT0()  asm volatile("cp.async.wait_group 0;" ::: "memory")

#define MMA_TF32(c, a, b0v, b1v) \
    asm volatile("mma.sync.aligned.m16n8k8.row.col.f32.tf32.tf32.f32 " \
        "{%0,%1,%2,%3}, {%4,%5,%6,%7}, {%8,%9}, {%0,%1,%2,%3};" \
        : "+f"((c)[0]), "+f"((c)[1]), "+f"((c)[2]), "+f"((c)[3]) \
        : "r"((a)[0]), "r"((a)[1]), "r"((a)[2]), "r"((a)[3]), "r"(b0v), "r"(b1v))

extern __shared__ char dsm[];

// ---------------- X pre-round (fp32 -> tf32 values) ----------------
__global__ void round_x_kernel(const float* __restrict__ x) {
    int i = (blockIdx.x * 256 + threadIdx.x) * 4;
    float4 v = *(const float4*)(x + i);
    v.x = tf32r(v.x); v.y = tf32r(v.y); v.z = tf32r(v.z); v.w = tf32r(v.w);
    *(float4*)(&g_xr[0][0] + i) = v;
}

// ---------------- gating ----------------
__global__ void gating_kernel(const float* __restrict__ x,
                              const float* __restrict__ wg) {
    int s = blockIdx.x;
    __shared__ float xs[HID];
    __shared__ float logits_s[NE];
    int tid = threadIdx.x;

    for (int i = tid; i < HID; i += 256) xs[i] = x[(size_t)s * HID + i];
    __syncthreads();

    int e = tid >> 2, sub = tid & 3;
    const float* w = wg + (size_t)e * HID;
    float acc = 0.f;
    for (int i = sub; i < HID; i += 4) acc += xs[i] * w[i];
    acc += __shfl_down_sync(0xffffffffu, acc, 2);
    acc += __shfl_down_sync(0xffffffffu, acc, 1);
    if (sub == 0) logits_s[e] = acc;
    __syncthreads();

    if (tid < 32) {
        float v0 = logits_s[tid];
        float v1 = logits_s[tid + 32];
        float tv[TK]; int tix[TK];
#pragma unroll
        for (int r = 0; r < TK; r++) {
            float bv; int bi;
            if (v0 >= v1) { bv = v0; bi = tid; }
            else          { bv = v1; bi = tid + 32; }
#pragma unroll
            for (int off = 16; off > 0; off >>= 1) {
                float ov = __shfl_down_sync(0xffffffffu, bv, off);
                int   oi = __shfl_down_sync(0xffffffffu, bi, off);
                if (ov > bv || (ov == bv && oi < bi)) { bv = ov; bi = oi; }
            }
            bv = __shfl_sync(0xffffffffu, bv, 0);
            bi = __shfl_sync(0xffffffffu, bi, 0);
            if (bi == tid)      v0 = -INFINITY;
            if (bi == tid + 32) v1 = -INFINITY;
            tv[r] = bv; tix[r] = bi;
        }
        if (tid == 0) {
            float m = tv[0], wv[TK], D = 0.f;
#pragma unroll
            for (int r = 0; r < TK; r++) { wv[r] = expf(tv[r] - m); D += wv[r]; }
            D = fmaxf(D, 1.1920929e-7f);
#pragma unroll
            for (int r = 0; r < TK; r++) { g_topw[s][r] = wv[r] / D; g_topi[s][r] = tix[r]; }
        }
    }
}

// ---------------- priority ----------------
__global__ void priority_kernel(const int* __restrict__ capacity) {
    int e = blockIdx.x, lane = threadIdx.x;
    int cap = capacity[0];
    if (cap > CAPMAX) cap = CAPMAX;
    if (cap < 0) cap = 0;

    int offset = 0;
    for (int base = 0; base < S_TOK * TK; base += 32) {
        int p = base + lane;
        int k = p / S_TOK;
        int s = p - k * S_TOK;
        bool match = (g_topi[s][k] == e);
        unsigned mask = __ballot_sync(0xffffffffu, match);
        if (match) {
            int c = offset + __popc(mask & ((1u << lane) - 1u));
            if (c < cap) { g_slot[s][k] = c; g_etok[e][c] = s; }
            else         { g_slot[s][k] = -1; }
        }
        offset += __popc(mask);
    }
    if (lane == 0) g_ecount[e] = (offset < cap) ? offset : cap;
}

// ---------------- GEMM1 (tf32 mma.sync, cp.async A) + SwiGLU ----------------
__global__ __launch_bounds__(256, 2)
void gemm1_mma(const float* __restrict__ Wsh,
               const float* __restrict__ Wex) {
    int b = blockIdx.x;
    int M, x, y; const int* gather; const float* Wp; float* Out;
    if (b < G1_EXP_BLKS) {
        int e   = b / 96;
        int rem = b - e * 96;
        y = rem / 48; x = rem - y * 48;
        M = g_ecount[e]; gather = g_etok[e];
        Wp = Wex + (size_t)e * I2 * HID; Out = &g_ex_gated[e][0][0];
    } else {
        int b2 = b - G1_EXP_BLKS;
        y = b2 / 48; x = b2 - y * 48;
        M = S_TOK; gather = nullptr; Wp = Wsh; Out = &g_sh_gated[0][0];
    }
    int m0 = y * BM;
    if (m0 >= M) return;
    int n0 = x * 64;
    int Mrem = M - m0; if (Mrem > BM) Mrem = BM;
    int ntiles = (Mrem + 15) >> 4;
    int npass  = (ntiles + 1) >> 1;

    uint32_t sb = smem_u32(dsm);
    int t = threadIdx.x, lane = t & 31, wid = t >> 5;
    int wm = wid >> 2, wn = wid & 3;
    int lq = lane >> 2, lr = lane & 3;

    int kseg = t & 7;
    int r32  = t >> 3;

    const float* ap[4]; int apred[4];
#pragma unroll
    for (int p = 0; p < 4; p++) {
        int m = m0 + p * 32 + r32;
        apred[p] = (p < npass && m < M);
        int mm = apred[p] ? (gather ? gather[m] : m) : 0;
        ap[p] = &g_xr[0][0] + (size_t)mm * HID + kseg * 4;
    }
    const float* bp[4];
#pragma unroll
    for (int p = 0; p < 4; p++) {
        int row = p * 32 + r32;
        int wr = (row < 64) ? (n0 + row) : (n0 + row - 64 + I1);
        bp[p] = Wp + (size_t)wr * HID + kseg * 4;
    }

    float acc1[4][2][4], acc2[4][2][4];
#pragma unroll
    for (int mt = 0; mt < 4; mt++)
#pragma unroll
        for (int nt = 0; nt < 2; nt++)
#pragma unroll
            for (int i = 0; i < 4; i++) { acc1[mt][nt][i] = 0.f; acc2[mt][nt][i] = 0.f; }

    float4 vbr[4];
    uint32_t sts_off = (uint32_t)(r32 * PR + kseg * 4) * 4;

    // prologue: chunk 0 -> buf 0
#pragma unroll
    for (int p = 0; p < 4; p++)
        cpa16(sb + p * 32 * PR * 4 + sts_off, ap[p], apred[p]);
    CP_COMMIT();
#pragma unroll
    for (int p = 0; p < 4; p++) vbr[p] = *(const float4*)(bp[p]);
    {
        uint32_t Bb = sb + A_BYTES;
#pragma unroll
        for (int p = 0; p < 4; p++) cvt_sts(Bb + p * 32 * PR * 4 + sts_off, vbr[p]);
    }
    CP_WAIT0();
    __syncthreads();

#pragma unroll 1
    for (int kc = 0; kc < NC1; kc++) {
        int buf = kc & 1;
        if (kc + 1 < NC1) {
            int ko = (kc + 1) * BK;
            uint32_t Ab2 = sb + (buf ^ 1) * STG;
#pragma unroll
            for (int p = 0; p < 4; p++)
                cpa16(Ab2 + p * 32 * PR * 4 + sts_off, ap[p] + ko, apred[p]);
            CP_COMMIT();
#pragma unroll
            for (int p = 0; p < 4; p++) vbr[p] = *(const float4*)(bp[p] + ko);
        }
        uint32_t Ab = sb + buf * STG;
        uint32_t Bb = Ab + A_BYTES;
#pragma unroll
        for (int ks = 0; ks < 4; ks++) {
            uint32_t kcol = (uint32_t)(ks * 8 + lr) * 4;
            uint32_t b1v[2][2], b2v[2][2];
#pragma unroll
            for (int nt = 0; nt < 2; nt++) {
                uint32_t base1 = Bb + (uint32_t)((wn * 16 + nt * 8 + lq) * PR) * 4 + kcol;
                b1v[nt][0] = lds_u32(base1);
                b1v[nt][1] = lds_u32(base1 + 16);
                uint32_t base2 = base1 + 64 * PR * 4;
                b2v[nt][0] = lds_u32(base2);
                b2v[nt][1] = lds_u32(base2 + 16);
            }
#pragma unroll
            for (int mt = 0; mt < 4; mt++) {
                int ti = mt * 2 + wm;
                if (ti < ntiles) {
                    uint32_t a[4];
                    uint32_t base = Ab + (uint32_t)((ti * 16 + lq) * PR) * 4 + kcol;
                    a[0] = lds_u32(base);
                    a[1] = lds_u32(base + 8 * PR * 4);
                    a[2] = lds_u32(base + 16);
                    a[3] = lds_u32(base + 8 * PR * 4 + 16);
#pragma unroll
                    for (int nt = 0; nt < 2; nt++) {
                        MMA_TF32(acc1[mt][nt], a, b1v[nt][0], b1v[nt][1]);
                        MMA_TF32(acc2[mt][nt], a, b2v[nt][0], b2v[nt][1]);
                    }
                }
            }
        }
        if (kc + 1 < NC1) {
            uint32_t Bb2 = sb + (buf ^ 1) * STG + A_BYTES;
#pragma unroll
            for (int p = 0; p < 4; p++) cvt_sts(Bb2 + p * 32 * PR * 4 + sts_off, vbr[p]);
        }
        CP_WAIT0();
        __syncthreads();
    }

    // epilogue: fused SwiGLU; outputs pre-rounded to tf32
#pragma unroll
    for (int mt = 0; mt < 4; mt++) {
        int ti = mt * 2 + wm;
        if (ti >= ntiles) continue;
        int rbase = m0 + ti * 16 + lq;
#pragma unroll
        for (int nt = 0; nt < 2; nt++) {
            int col = n0 + wn * 16 + nt * 8 + lr * 2;
#pragma unroll
            for (int half = 0; half < 2; half++) {
                int r = rbase + half * 8;
                if (r < M) {
                    float g1a = acc1[mt][nt][half * 2 + 0];
                    float g1b = acc1[mt][nt][half * 2 + 1];
                    float g2a = acc2[mt][nt][half * 2 + 0];
                    float g2b = acc2[mt][nt][half * 2 + 1];
                    float2 o;
                    o.x = tf32r(g1a * (g2a / (1.f + expf(-g2a))));
                    o.y = tf32r(g1b * (g2b / (1.f + expf(-g2b))));
                    *(float2*)&Out[(size_t)r * I1 + col] = o;
                }
            }
        }
    }
}

// ---------------- GEMM2 (tf32 mma.sync, cp.async A): 128 x 128 ----------------
__global__ __launch_bounds__(256, 2)
void gemm2_mma(const float* __restrict__ Wsh,
               const float* __restrict__ Wex,
               float* __restrict__ dout) {
    int b = blockIdx.x;
    int M, x, y; const float* G; const float* Wp; float* Out;
    if (b < G2_EXP_BLKS) {
        int e   = b / 12;
        int rem = b - e * 12;
        y = rem / 6; x = rem - y * 6;
        M = g_ecount[e]; G = &g_ex_gated[e][0][0];
        Wp = Wex + (size_t)e * HID * I1; Out = &g_ex_out[e][0][0];
    } else {
        int b2 = b - G2_EXP_BLKS;
        y = b2 / 6; x = b2 - y * 6;
        M = S_TOK; G = &g_sh_gated[0][0]; Wp = Wsh; Out = dout;
    }
    int m0 = y * BM;
    if (m0 >= M) return;
    int n0 = x * 128;
    int Mrem = M - m0; if (Mrem > BM) Mrem = BM;
    int ntiles = (Mrem + 15) >> 4;
    int npass  = (ntiles + 1) >> 1;

    uint32_t sb = smem_u32(dsm);
    int t = threadIdx.x, lane = t & 31, wid = t >> 5;
    int wm = wid >> 2, wn = wid & 3;
    int lq = lane >> 2, lr = lane & 3;

    int kseg = t & 7;
    int r32  = t >> 3;

    const float* ap[4]; int apred[4];
#pragma unroll
    for (int p = 0; p < 4; p++) {
        int m = m0 + p * 32 + r32;
        apred[p] = (p < npass && m < M);
        int mm = apred[p] ? m : 0;
        ap[p] = G + (size_t)mm * I1 + kseg * 4;
    }
    const float* bp[4];
#pragma unroll
    for (int p = 0; p < 4; p++)
        bp[p] = Wp + (size_t)(n0 + p * 32 + r32) * I1 + kseg * 4;

    float acc[4][4][4];
#pragma unroll
    for (int mt = 0; mt < 4; mt++)
#pragma unroll
        for (int nt = 0; nt < 4; nt++)
#pragma unroll
            for (int i = 0; i < 4; i++) acc[mt][nt][i] = 0.f;

    float4 vbr[4];
    uint32_t sts_off = (uint32_t)(r32 * PR + kseg * 4) * 4;

#pragma unroll
    for (int p = 0; p < 4; p++)
        cpa16(sb + p * 32 * PR * 4 + sts_off, ap[p], apred[p]);
    CP_COMMIT();
#pragma unroll
    for (int p = 0; p < 4; p++) vbr[p] = *(const float4*)(bp[p]);
    {
        uint32_t Bb = sb + A_BYTES;
#pragma unroll
        for (int p = 0; p < 4; p++) cvt_sts(Bb + p * 32 * PR * 4 + sts_off, vbr[p]);
    }
    CP_WAIT0();
    __syncthreads();

#pragma unroll 1
    for (int kc = 0; kc < NC2; kc++) {
        int buf = kc & 1;
        if (kc + 1 < NC2) {
            int ko = (kc + 1) * BK;
            uint32_t Ab2 = sb + (buf ^ 1) * STG;
#pragma unroll
            for (int p = 0; p < 4; p++)
                cpa16(Ab2 + p * 32 * PR * 4 + sts_off, ap[p] + ko, apred[p]);
            CP_COMMIT();
#pragma unroll
            for (int p = 0; p < 4; p++) vbr[p] = *(const float4*)(bp[p] + ko);
        }
        uint32_t Ab = sb + buf * STG;
        uint32_t Bb = Ab + A_BYTES;
#pragma unroll
        for (int ks = 0; ks < 4; ks++) {
            uint32_t kcol = (uint32_t)(ks * 8 + lr) * 4;
            uint32_t bv[4][2];
#pragma unroll
            for (int nt = 0; nt < 4; nt++) {
                uint32_t base = Bb + (uint32_t)((wn * 32 + nt * 8 + lq) * PR) * 4 + kcol;
                bv[nt][0] = lds_u32(base);
                bv[nt][1] = lds_u32(base + 16);
            }
#pragma unroll
            for (int mt = 0; mt < 4; mt++) {
                int ti = mt * 2 + wm;
                if (ti < ntiles) {
                    uint32_t a[4];
                    uint32_t base = Ab + (uint32_t)((ti * 16 + lq) * PR) * 4 + kcol;
                    a[0] = lds_u32(base);
                    a[1] = lds_u32(base + 8 * PR * 4);
                    a[2] = lds_u32(base + 16);
                    a[3] = lds_u32(base + 8 * PR * 4 + 16);
#pragma unroll
                    for (int nt = 0; nt < 4; nt++)
                        MMA_TF32(acc[mt][nt], a, bv[nt][0], bv[nt][1]);
                }
            }
        }
        if (kc + 1 < NC2) {
            uint32_t Bb2 = sb + (buf ^ 1) * STG + A_BYTES;
#pragma unroll
            for (int p = 0; p < 4; p++) cvt_sts(Bb2 + p * 32 * PR * 4 + sts_off, vbr[p]);
        }
        CP_WAIT0();
        __syncthreads();
    }

#pragma unroll
    for (int mt = 0; mt < 4; mt++) {
        int ti = mt * 2 + wm;
        if (ti >= ntiles) continue;
        int rbase = m0 + ti * 16 + lq;
#pragma unroll
        for (int nt = 0; nt < 4; nt++) {
            int col = n0 + wn * 32 + nt * 8 + lr * 2;
#pragma unroll
            for (int half = 0; half < 2; half++) {
                int r = rbase + half * 8;
                if (r < M) {
                    float2 o;
                    o.x = acc[mt][nt][half * 2 + 0];
                    o.y = acc[mt][nt][half * 2 + 1];
                    *(float2*)&Out[(size_t)r * HID + col] = o;
                }
            }
        }
    }
}

// ---------------- combine ----------------
__global__ void combine_kernel(float* __restrict__ out) {
    int s = blockIdx.x, tid = threadIdx.x;
    __shared__ int ke[TK], kc_[TK];
    __shared__ float kw[TK];
    if (tid < TK) { ke[tid] = g_topi[s][tid]; kc_[tid] = g_slot[s][tid]; kw[tid] = g_topw[s][tid]; }
    __syncthreads();
    for (int h = tid; h < HID; h += 256) {
        float acc = out[(size_t)s * HID + h];
#pragma unroll
        for (int k = 0; k < TK; k++) {
            int c = kc_[k];
            if (c >= 0) acc += kw[k] * g_ex_out[ke[k]][c][h];
        }
        out[(size_t)s * HID + h] = acc;
    }
}

// ---------------------------------------------------------------------------
extern "C" void kernel_launch(void* const* d_in, const int* in_sizes, int n_in,
                              void* d_out, int out_size) {
    const float* x      = (const float*)d_in[0];
    const float* w_gu   = (const float*)d_in[1];
    const float* w_down = (const float*)d_in[2];
    const float* wg     = (const float*)d_in[3];
    const float* w1     = (const float*)d_in[4];
    const float* w2     = (const float*)d_in[5];
    const int*   cap    = (const int*)d_in[6];
    float* out = (float*)d_out;

    cudaFuncSetAttribute(gemm1_mma, cudaFuncAttributeMaxDynamicSharedMemorySize, SMEM_BYTES);
    cudaFuncSetAttribute(gemm2_mma, cudaFuncAttributeMaxDynamicSharedMemorySize, SMEM_BYTES);

    gating_kernel<<<S_TOK, 256>>>(x, wg);
    round_x_kernel<<<S_TOK * HID / 1024, 256>>>(x);
    priority_kernel<<<NE, 32>>>(cap);

    gemm1_mma<<<G1_EXP_BLKS + G1_SH_BLKS, 256, SMEM_BYTES>>>(w_gu, w1);
    gemm2_mma<<<G2_EXP_BLKS + G2_SH_BLKS, 256, SMEM_BYTES>>>(w_down, w2, out);

    combine_kernel<<<S_TOK, 256>>>(out);
}

// round 10
// speedup vs baseline: 1.5707x; 1.0320x over previous
#include <cuda_runtime.h>
#include <cstdint>
#include <math.h>

// ---------------- problem constants ----------------
#define S_TOK   1024
#define HID     768
#define NE      64
#define TK      8
#define CAPMAX  256
#define I1      3072
#define I2      6144

// ---------------- GEMM tiling ----------------
#define BM   128
#define BK   32
#define PR   36                        // padded row length (floats)
#define A_BYTES (BM * PR * 4)          // 18432
#define B_BYTES (128 * PR * 4)         // 18432
#define STG     (A_BYTES + B_BYTES)    // 36864
#define NSTAGE  3
#define SMEM_BYTES (NSTAGE * STG)      // 110592
#define NC1 (HID / BK)                 // 24
#define NC2 (I1 / BK)                  // 96

// merged-grid sizes
#define G1_EXP_BLKS (48 * 2 * NE)      // 6144
#define G1_SH_BLKS  (48 * 8)           // 384
#define G2_EXP_BLKS (6 * 2 * NE)       // 768
#define G2_SH_BLKS  (6 * 8)            // 48

// ---------------- device scratch ----------------
__device__ __align__(16)  float g_topw[S_TOK][TK];
__device__ __align__(16)  int   g_topi[S_TOK][TK];
__device__ __align__(16)  int   g_slot[S_TOK][TK];
__device__ __align__(16)  int   g_ecount[NE];
__device__ __align__(16)  int   g_etok[NE][CAPMAX];
__device__ __align__(256) float g_xr[S_TOK][HID];             // tf32-rounded X
__device__ __align__(256) float g_sh_gated[S_TOK][I1];
__device__ __align__(256) float g_ex_gated[NE][CAPMAX][I1];
__device__ __align__(256) float g_ex_out[NE][CAPMAX][HID];

// ---------------- helpers ----------------
__device__ __forceinline__ uint32_t smem_u32(const void* p) {
    uint32_t a;
    asm("{ .reg .u64 t; cvta.to.shared.u64 t, %1; cvt.u32.u64 %0, t; }" : "=r"(a) : "l"(p));
    return a;
}
__device__ __forceinline__ uint32_t lds_u32(uint32_t addr) {
    uint32_t v;
    asm volatile("ld.shared.b32 %0, [%1];" : "=r"(v) : "r"(addr));
    return v;
}
// LDS fp32 then round to tf32 (RNA) in-register
__device__ __forceinline__ uint32_t lds_cvt(uint32_t addr) {
    float f;
    asm volatile("ld.shared.f32 %0, [%1];" : "=f"(f) : "r"(addr));
    uint32_t v;
    asm volatile("cvt.rna.tf32.f32 %0, %1;" : "=r"(v) : "f"(f));
    return v;
}
__device__ __forceinline__ float tf32r(float x) {
    uint32_t v;
    asm("cvt.rna.tf32.f32 %0, %1;" : "=r"(v) : "f"(x));
    return __uint_as_float(v);
}
// async 16B copy gmem->smem; pred=0 zero-fills (no src read)
__device__ __forceinline__ void cpa16(uint32_t dst, const float* src, int pred) {
    int sz = pred ? 16 : 0;
    asm volatile("cp.async.cg.shared.global [%0], [%1], 16, %2;"
                 :: "r"(dst), "l"(src), "r"(sz) : "memory");
}
#define CP_COMMIT() asm volatile("cp.async.commit_group;" ::: "memory")
#define CP_WAIT1()  asm volatile("cp.async.wait_group 1;" ::: "memory")

#define MMA_TF32(c, a, b0v, b1v) \
    asm volatile("mma.sync.aligned.m16n8k8.row.col.f32.tf32.tf32.f32 " \
        "{%0,%1,%2,%3}, {%4,%5,%6,%7}, {%8,%9}, {%0,%1,%2,%3};" \
        : "+f"((c)[0]), "+f"((c)[1]), "+f"((c)[2]), "+f"((c)[3]) \
        : "r"((a)[0]), "r"((a)[1]), "r"((a)[2]), "r"((a)[3]), "r"(b0v), "r"(b1v))

extern __shared__ char dsm[];

// ---------------- X pre-round (fp32 -> tf32 values) ----------------
__global__ void round_x_kernel(const float* __restrict__ x) {
    int i = (blockIdx.x * 256 + threadIdx.x) * 4;
    float4 v = *(const float4*)(x + i);
    v.x = tf32r(v.x); v.y = tf32r(v.y); v.z = tf32r(v.z); v.w = tf32r(v.w);
    *(float4*)(&g_xr[0][0] + i) = v;
}

// ---------------- gating ----------------
__global__ void gating_kernel(const float* __restrict__ x,
                              const float* __restrict__ wg) {
    int s = blockIdx.x;
    __shared__ float xs[HID];
    __shared__ float logits_s[NE];
    int tid = threadIdx.x;

    for (int i = tid; i < HID; i += 256) xs[i] = x[(size_t)s * HID + i];
    __syncthreads();

    int e = tid >> 2, sub = tid & 3;
    const float* w = wg + (size_t)e * HID;
    float acc = 0.f;
    for (int i = sub; i < HID; i += 4) acc += xs[i] * w[i];
    acc += __shfl_down_sync(0xffffffffu, acc, 2);
    acc += __shfl_down_sync(0xffffffffu, acc, 1);
    if (sub == 0) logits_s[e] = acc;
    __syncthreads();

    if (tid < 32) {
        float v0 = logits_s[tid];
        float v1 = logits_s[tid + 32];
        float tv[TK]; int tix[TK];
#pragma unroll
        for (int r = 0; r < TK; r++) {
            float bv; int bi;
            if (v0 >= v1) { bv = v0; bi = tid; }
            else          { bv = v1; bi = tid + 32; }
#pragma unroll
            for (int off = 16; off > 0; off >>= 1) {
                float ov = __shfl_down_sync(0xffffffffu, bv, off);
                int   oi = __shfl_down_sync(0xffffffffu, bi, off);
                if (ov > bv || (ov == bv && oi < bi)) { bv = ov; bi = oi; }
            }
            bv = __shfl_sync(0xffffffffu, bv, 0);
            bi = __shfl_sync(0xffffffffu, bi, 0);
            if (bi == tid)      v0 = -INFINITY;
            if (bi == tid + 32) v1 = -INFINITY;
            tv[r] = bv; tix[r] = bi;
        }
        if (tid == 0) {
            float m = tv[0], wv[TK], D = 0.f;
#pragma unroll
            for (int r = 0; r < TK; r++) { wv[r] = expf(tv[r] - m); D += wv[r]; }
            D = fmaxf(D, 1.1920929e-7f);
#pragma unroll
            for (int r = 0; r < TK; r++) { g_topw[s][r] = wv[r] / D; g_topi[s][r] = tix[r]; }
        }
    }
}

// ---------------- priority ----------------
__global__ void priority_kernel(const int* __restrict__ capacity) {
    int e = blockIdx.x, lane = threadIdx.x;
    int cap = capacity[0];
    if (cap > CAPMAX) cap = CAPMAX;
    if (cap < 0) cap = 0;

    int offset = 0;
    for (int base = 0; base < S_TOK * TK; base += 32) {
        int p = base + lane;
        int k = p / S_TOK;
        int s = p - k * S_TOK;
        bool match = (g_topi[s][k] == e);
        unsigned mask = __ballot_sync(0xffffffffu, match);
        if (match) {
            int c = offset + __popc(mask & ((1u << lane) - 1u));
            if (c < cap) { g_slot[s][k] = c; g_etok[e][c] = s; }
            else         { g_slot[s][k] = -1; }
        }
        offset += __popc(mask);
    }
    if (lane == 0) g_ecount[e] = (offset < cap) ? offset : cap;
}

// ---------------- GEMM1 (tf32 mma.sync, all-cp.async 3-stage) + SwiGLU ----------------
__global__ __launch_bounds__(256, 2)
void gemm1_mma(const float* __restrict__ Wsh,
               const float* __restrict__ Wex) {
    int b = blockIdx.x;
    int M, x, y; const int* gather; const float* Wp; float* Out;
    if (b < G1_EXP_BLKS) {
        int e   = b / 96;
        int rem = b - e * 96;
        y = rem / 48; x = rem - y * 48;
        M = g_ecount[e]; gather = g_etok[e];
        Wp = Wex + (size_t)e * I2 * HID; Out = &g_ex_gated[e][0][0];
    } else {
        int b2 = b - G1_EXP_BLKS;
        y = b2 / 48; x = b2 - y * 48;
        M = S_TOK; gather = nullptr; Wp = Wsh; Out = &g_sh_gated[0][0];
    }
    int m0 = y * BM;
    if (m0 >= M) return;
    int n0 = x * 64;
    int Mrem = M - m0; if (Mrem > BM) Mrem = BM;
    int ntiles = (Mrem + 15) >> 4;
    int npass  = (ntiles + 1) >> 1;

    uint32_t sb = smem_u32(dsm);
    int t = threadIdx.x, lane = t & 31, wid = t >> 5;
    int wm = wid >> 2, wn = wid & 3;
    int lq = lane >> 2, lr = lane & 3;

    int kseg = t & 7;
    int r32  = t >> 3;

    const float* ap[4]; int apred[4];
#pragma unroll
    for (int p = 0; p < 4; p++) {
        int m = m0 + p * 32 + r32;
        apred[p] = (p < npass && m < M);
        int mm = apred[p] ? (gather ? gather[m] : m) : 0;
        ap[p] = &g_xr[0][0] + (size_t)mm * HID + kseg * 4;
    }
    const float* bp[4];
#pragma unroll
    for (int p = 0; p < 4; p++) {
        int row = p * 32 + r32;
        int wr = (row < 64) ? (n0 + row) : (n0 + row - 64 + I1);
        bp[p] = Wp + (size_t)wr * HID + kseg * 4;
    }

    float acc1[4][2][4], acc2[4][2][4];
#pragma unroll
    for (int mt = 0; mt < 4; mt++)
#pragma unroll
        for (int nt = 0; nt < 2; nt++)
#pragma unroll
            for (int i = 0; i < 4; i++) { acc1[mt][nt][i] = 0.f; acc2[mt][nt][i] = 0.f; }

    uint32_t sts_off = (uint32_t)(r32 * PR + kseg * 4) * 4;

    // prologue: issue chunks 0 and 1
#pragma unroll
    for (int c = 0; c < 2; c++) {
        uint32_t Sb = sb + c * STG;
        int ko = c * BK;
#pragma unroll
        for (int p = 0; p < 4; p++) cpa16(Sb + p * 32 * PR * 4 + sts_off, ap[p] + ko, apred[p]);
#pragma unroll
        for (int p = 0; p < 4; p++) cpa16(Sb + A_BYTES + p * 32 * PR * 4 + sts_off, bp[p] + ko, 1);
        CP_COMMIT();
    }
    CP_WAIT1();
    __syncthreads();

    int buf = 0;
#pragma unroll 1
    for (int kc = 0; kc < NC1; kc++) {
        uint32_t Ab = sb + buf * STG;
        uint32_t Bb = Ab + A_BYTES;
#pragma unroll
        for (int ks = 0; ks < 4; ks++) {
            uint32_t kcol = (uint32_t)(ks * 8 + lr) * 4;
            uint32_t b1v[2][2], b2v[2][2];
#pragma unroll
            for (int nt = 0; nt < 2; nt++) {
                uint32_t base1 = Bb + (uint32_t)((wn * 16 + nt * 8 + lq) * PR) * 4 + kcol;
                b1v[nt][0] = lds_cvt(base1);
                b1v[nt][1] = lds_cvt(base1 + 16);
                uint32_t base2 = base1 + 64 * PR * 4;
                b2v[nt][0] = lds_cvt(base2);
                b2v[nt][1] = lds_cvt(base2 + 16);
            }
#pragma unroll
            for (int mt = 0; mt < 4; mt++) {
                int ti = mt * 2 + wm;
                if (ti < ntiles) {
                    uint32_t a[4];
                    uint32_t base = Ab + (uint32_t)((ti * 16 + lq) * PR) * 4 + kcol;
                    a[0] = lds_u32(base);
                    a[1] = lds_u32(base + 8 * PR * 4);
                    a[2] = lds_u32(base + 16);
                    a[3] = lds_u32(base + 8 * PR * 4 + 16);
#pragma unroll
                    for (int nt = 0; nt < 2; nt++) {
                        MMA_TF32(acc1[mt][nt], a, b1v[nt][0], b1v[nt][1]);
                        MMA_TF32(acc2[mt][nt], a, b2v[nt][0], b2v[nt][1]);
                    }
                }
            }
        }
        // issue chunk kc+2 into the buffer freed at end of previous iteration
        if (kc + 2 < NC1) {
            int nb = buf + 2; if (nb >= NSTAGE) nb -= NSTAGE;
            uint32_t Sb = sb + nb * STG;
            int ko = (kc + 2) * BK;
#pragma unroll
            for (int p = 0; p < 4; p++) cpa16(Sb + p * 32 * PR * 4 + sts_off, ap[p] + ko, apred[p]);
#pragma unroll
            for (int p = 0; p < 4; p++) cpa16(Sb + A_BYTES + p * 32 * PR * 4 + sts_off, bp[p] + ko, 1);
        }
        CP_COMMIT();
        CP_WAIT1();
        __syncthreads();
        if (++buf == NSTAGE) buf = 0;
    }

    // epilogue: fused SwiGLU; outputs pre-rounded to tf32
#pragma unroll
    for (int mt = 0; mt < 4; mt++) {
        int ti = mt * 2 + wm;
        if (ti >= ntiles) continue;
        int rbase = m0 + ti * 16 + lq;
#pragma unroll
        for (int nt = 0; nt < 2; nt++) {
            int col = n0 + wn * 16 + nt * 8 + lr * 2;
#pragma unroll
            for (int half = 0; half < 2; half++) {
                int r = rbase + half * 8;
                if (r < M) {
                    float g1a = acc1[mt][nt][half * 2 + 0];
                    float g1b = acc1[mt][nt][half * 2 + 1];
                    float g2a = acc2[mt][nt][half * 2 + 0];
                    float g2b = acc2[mt][nt][half * 2 + 1];
                    float2 o;
                    o.x = tf32r(g1a * (g2a / (1.f + expf(-g2a))));
                    o.y = tf32r(g1b * (g2b / (1.f + expf(-g2b))));
                    *(float2*)&Out[(size_t)r * I1 + col] = o;
                }
            }
        }
    }
}

// ---------------- GEMM2 (tf32 mma.sync, all-cp.async 3-stage): 128 x 128 ----------------
__global__ __launch_bounds__(256, 2)
void gemm2_mma(const float* __restrict__ Wsh,
               const float* __restrict__ Wex,
               float* __restrict__ dout) {
    int b = blockIdx.x;
    int M, x, y; const float* G; const float* Wp; float* Out;
    if (b < G2_EXP_BLKS) {
        int e   = b / 12;
        int rem = b - e * 12;
        y = rem / 6; x = rem - y * 6;
        M = g_ecount[e]; G = &g_ex_gated[e][0][0];
        Wp = Wex + (size_t)e * HID * I1; Out = &g_ex_out[e][0][0];
    } else {
        int b2 = b - G2_EXP_BLKS;
        y = b2 / 6; x = b2 - y * 6;
        M = S_TOK; G = &g_sh_gated[0][0]; Wp = Wsh; Out = dout;
    }
    int m0 = y * BM;
    if (m0 >= M) return;
    int n0 = x * 128;
    int Mrem = M - m0; if (Mrem > BM) Mrem = BM;
    int ntiles = (Mrem + 15) >> 4;
    int npass  = (ntiles + 1) >> 1;

    uint32_t sb = smem_u32(dsm);
    int t = threadIdx.x, lane = t & 31, wid = t >> 5;
    int wm = wid >> 2, wn = wid & 3;
    int lq = lane >> 2, lr = lane & 3;

    int kseg = t & 7;
    int r32  = t >> 3;

    const float* ap[4]; int apred[4];
#pragma unroll
    for (int p = 0; p < 4; p++) {
        int m = m0 + p * 32 + r32;
        apred[p] = (p < npass && m < M);
        int mm = apred[p] ? m : 0;
        ap[p] = G + (size_t)mm * I1 + kseg * 4;
    }
    const float* bp[4];
#pragma unroll
    for (int p = 0; p < 4; p++)
        bp[p] = Wp + (size_t)(n0 + p * 32 + r32) * I1 + kseg * 4;

    float acc[4][4][4];
#pragma unroll
    for (int mt = 0; mt < 4; mt++)
#pragma unroll
        for (int nt = 0; nt < 4; nt++)
#pragma unroll
            for (int i = 0; i < 4; i++) acc[mt][nt][i] = 0.f;

    uint32_t sts_off = (uint32_t)(r32 * PR + kseg * 4) * 4;

    // prologue: issue chunks 0 and 1
#pragma unroll
    for (int c = 0; c < 2; c++) {
        uint32_t Sb = sb + c * STG;
        int ko = c * BK;
#pragma unroll
        for (int p = 0; p < 4; p++) cpa16(Sb + p * 32 * PR * 4 + sts_off, ap[p] + ko, apred[p]);
#pragma unroll
        for (int p = 0; p < 4; p++) cpa16(Sb + A_BYTES + p * 32 * PR * 4 + sts_off, bp[p] + ko, 1);
        CP_COMMIT();
    }
    CP_WAIT1();
    __syncthreads();

    int buf = 0;
#pragma unroll 1
    for (int kc = 0; kc < NC2; kc++) {
        uint32_t Ab = sb + buf * STG;
        uint32_t Bb = Ab + A_BYTES;
#pragma unroll
        for (int ks = 0; ks < 4; ks++) {
            uint32_t kcol = (uint32_t)(ks * 8 + lr) * 4;
            uint32_t bv[4][2];
#pragma unroll
            for (int nt = 0; nt < 4; nt++) {
                uint32_t base = Bb + (uint32_t)((wn * 32 + nt * 8 + lq) * PR) * 4 + kcol;
                bv[nt][0] = lds_cvt(base);
                bv[nt][1] = lds_cvt(base + 16);
            }
#pragma unroll
            for (int mt = 0; mt < 4; mt++) {
                int ti = mt * 2 + wm;
                if (ti < ntiles) {
                    uint32_t a[4];
                    uint32_t base = Ab + (uint32_t)((ti * 16 + lq) * PR) * 4 + kcol;
                    a[0] = lds_u32(base);
                    a[1] = lds_u32(base + 8 * PR * 4);
                    a[2] = lds_u32(base + 16);
                    a[3] = lds_u32(base + 8 * PR * 4 + 16);
#pragma unroll
                    for (int nt = 0; nt < 4; nt++)
                        MMA_TF32(acc[mt][nt], a, bv[nt][0], bv[nt][1]);
                }
            }
        }
        if (kc + 2 < NC2) {
            int nb = buf + 2; if (nb >= NSTAGE) nb -= NSTAGE;
            uint32_t Sb = sb + nb * STG;
            int ko = (kc + 2) * BK;
#pragma unroll
            for (int p = 0; p < 4; p++) cpa16(Sb + p * 32 * PR * 4 + sts_off, ap[p] + ko, apred[p]);
#pragma unroll
            for (int p = 0; p < 4; p++) cpa16(Sb + A_BYTES + p * 32 * PR * 4 + sts_off, bp[p] + ko, 1);
        }
        CP_COMMIT();
        CP_WAIT1();
        __syncthreads();
        if (++buf == NSTAGE) buf = 0;
    }

#pragma unroll
    for (int mt = 0; mt < 4; mt++) {
        int ti = mt * 2 + wm;
        if (ti >= ntiles) continue;
        int rbase = m0 + ti * 16 + lq;
#pragma unroll
        for (int nt = 0; nt < 4; nt++) {
            int col = n0 + wn * 32 + nt * 8 + lr * 2;
#pragma unroll
            for (int half = 0; half < 2; half++) {
                int r = rbase + half * 8;
                if (r < M) {
                    float2 o;
                    o.x = acc[mt][nt][half * 2 + 0];
                    o.y = acc[mt][nt][half * 2 + 1];
                    *(float2*)&Out[(size_t)r * HID + col] = o;
                }
            }
        }
    }
}

// ---------------- combine ----------------
__global__ void combine_kernel(float* __restrict__ out) {
    int s = blockIdx.x, tid = threadIdx.x;
    __shared__ int ke[TK], kc_[TK];
    __shared__ float kw[TK];
    if (tid < TK) { ke[tid] = g_topi[s][tid]; kc_[tid] = g_slot[s][tid]; kw[tid] = g_topw[s][tid]; }
    __syncthreads();
    for (int h = tid; h < HID; h += 256) {
        float acc = out[(size_t)s * HID + h];
#pragma unroll
        for (int k = 0; k < TK; k++) {
            int c = kc_[k];
            if (c >= 0) acc += kw[k] * g_ex_out[ke[k]][c][h];
        }
        out[(size_t)s * HID + h] = acc;
    }
}

// ---------------------------------------------------------------------------
extern "C" void kernel_launch(void* const* d_in, const int* in_sizes, int n_in,
                              void* d_out, int out_size) {
    const float* x      = (const float*)d_in[0];
    const float* w_gu   = (const float*)d_in[1];
    const float* w_down = (const float*)d_in[2];
    const float* wg     = (const float*)d_in[3];
    const float* w1     = (const float*)d_in[4];
    const float* w2     = (const float*)d_in[5];
    const int*   cap    = (const int*)d_in[6];
    float* out = (float*)d_out;

    cudaFuncSetAttribute(gemm1_mma, cudaFuncAttributeMaxDynamicSharedMemorySize, SMEM_BYTES);
    cudaFuncSetAttribute(gemm2_mma, cudaFuncAttributeMaxDynamicSharedMemorySize, SMEM_BYTES);

    gating_kernel<<<S_TOK, 256>>>(x, wg);
    round_x_kernel<<<S_TOK * HID / 1024, 256>>>(x);
    priority_kernel<<<NE, 32>>>(cap);

    gemm1_mma<<<G1_EXP_BLKS + G1_SH_BLKS, 256, SMEM_BYTES>>>(w_gu, w1);
    gemm2_mma<<<G2_EXP_BLKS + G2_SH_BLKS, 256, SMEM_BYTES>>>(w_down, w2, out);

    combine_kernel<<<S_TOK, 256>>>(out);
}

// round 11
// speedup vs baseline: 2.1806x; 1.3883x over previous
#include <cuda_runtime.h>
#include <cuda_fp16.h>
#include <cstdint>
#include <math.h>

// ---------------- problem constants ----------------
#define S_TOK   1024
#define HID     768
#define NE      64
#define TK      8
#define CAPMAX  256
#define I1      3072
#define I2      6144

// ---------------- GEMM tiling (fp16 operands) ----------------
#define BM   128
#define BK   32                        // k elements per chunk
#define PRB  80                        // bytes per smem row (40 halves, conflict-free)
#define A_BYTES (BM * PRB)             // 10240
#define B_BYTES (128 * PRB)            // 10240
#define STG     (A_BYTES + B_BYTES)    // 20480
#define SMEM_BYTES (2 * STG)           // 40960 (double buffer)
#define NC1 (HID / BK)                 // 24
#define NC2 (I1 / BK)                  // 96

// merged-grid sizes
#define G1_EXP_BLKS (48 * 2 * NE)      // 6144
#define G1_SH_BLKS  (48 * 8)           // 384
#define G2_EXP_BLKS (6 * 2 * NE)       // 768
#define G2_SH_BLKS  (6 * 8)            // 48

// ---------------- device scratch ----------------
__device__ __align__(16)  float g_topw[S_TOK][TK];
__device__ __align__(16)  int   g_topi[S_TOK][TK];
__device__ __align__(16)  int   g_slot[S_TOK][TK];
__device__ __align__(16)  int   g_ecount[NE];
__device__ __align__(16)  int   g_etok[NE][CAPMAX];
__device__ __align__(256) __half g_xh[S_TOK][HID];            // fp16 X
__device__ __align__(256) __half g_sh_gated[S_TOK][I1];       // fp16 gated
__device__ __align__(256) __half g_ex_gated[NE][CAPMAX][I1];  // fp16 gated
__device__ __align__(256) float  g_ex_out[NE][CAPMAX][HID];

// ---------------- helpers ----------------
__device__ __forceinline__ uint32_t smem_u32(const void* p) {
    uint32_t a;
    asm("{ .reg .u64 t; cvta.to.shared.u64 t, %1; cvt.u32.u64 %0, t; }" : "=r"(a) : "l"(p));
    return a;
}
__device__ __forceinline__ uint32_t lds_u32(uint32_t addr) {
    uint32_t v;
    asm volatile("ld.shared.b32 %0, [%1];" : "=r"(v) : "r"(addr));
    return v;
}
// pack two floats to half2 (lo=x, hi=y)
__device__ __forceinline__ uint32_t f2h2(float x, float y) {
    uint32_t v;
    asm("cvt.rn.f16x2.f32 %0, %1, %2;" : "=r"(v) : "f"(y), "f"(x));
    return v;
}
// cvt float4 -> 4 halves, store 8B to smem
__device__ __forceinline__ void cvt_sts_h(uint32_t addr, float4 v) {
    uint32_t p0 = f2h2(v.x, v.y);
    uint32_t p1 = f2h2(v.z, v.w);
    asm volatile("st.shared.v2.b32 [%0], {%1, %2};" :: "r"(addr), "r"(p0), "r"(p1) : "memory");
}
// async 16B copy gmem->smem; pred=0 zero-fills
__device__ __forceinline__ void cpa16(uint32_t dst, const void* src, int pred) {
    int sz = pred ? 16 : 0;
    asm volatile("cp.async.cg.shared.global [%0], [%1], 16, %2;"
                 :: "r"(dst), "l"(src), "r"(sz) : "memory");
}
#define CP_COMMIT() asm volatile("cp.async.commit_group;" ::: "memory")
#define CP_WAIT0()  asm volatile("cp.async.wait_group 0;" ::: "memory")

#define MMA_F16(c, a, b0v, b1v) \
    asm volatile("mma.sync.aligned.m16n8k16.row.col.f32.f16.f16.f32 " \
        "{%0,%1,%2,%3}, {%4,%5,%6,%7}, {%8,%9}, {%0,%1,%2,%3};" \
        : "+f"((c)[0]), "+f"((c)[1]), "+f"((c)[2]), "+f"((c)[3]) \
        : "r"((a)[0]), "r"((a)[1]), "r"((a)[2]), "r"((a)[3]), "r"(b0v), "r"(b1v))

extern __shared__ char dsm[];

// ---------------- X -> fp16 ----------------
__global__ void round_x_kernel(const float* __restrict__ x) {
    int i = (blockIdx.x * 256 + threadIdx.x) * 4;
    float4 v = *(const float4*)(x + i);
    uint2 o;
    o.x = f2h2(v.x, v.y);
    o.y = f2h2(v.z, v.w);
    *(uint2*)(&g_xh[0][0] + i) = o;
}

// ---------------- gating (exact fp32) ----------------
__global__ void gating_kernel(const float* __restrict__ x,
                              const float* __restrict__ wg) {
    int s = blockIdx.x;
    __shared__ float xs[HID];
    __shared__ float logits_s[NE];
    int tid = threadIdx.x;

    for (int i = tid; i < HID; i += 256) xs[i] = x[(size_t)s * HID + i];
    __syncthreads();

    int e = tid >> 2, sub = tid & 3;
    const float* w = wg + (size_t)e * HID;
    float acc = 0.f;
    for (int i = sub; i < HID; i += 4) acc += xs[i] * w[i];
    acc += __shfl_down_sync(0xffffffffu, acc, 2);
    acc += __shfl_down_sync(0xffffffffu, acc, 1);
    if (sub == 0) logits_s[e] = acc;
    __syncthreads();

    if (tid < 32) {
        float v0 = logits_s[tid];
        float v1 = logits_s[tid + 32];
        float tv[TK]; int tix[TK];
#pragma unroll
        for (int r = 0; r < TK; r++) {
            float bv; int bi;
            if (v0 >= v1) { bv = v0; bi = tid; }
            else          { bv = v1; bi = tid + 32; }
#pragma unroll
            for (int off = 16; off > 0; off >>= 1) {
                float ov = __shfl_down_sync(0xffffffffu, bv, off);
                int   oi = __shfl_down_sync(0xffffffffu, bi, off);
                if (ov > bv || (ov == bv && oi < bi)) { bv = ov; bi = oi; }
            }
            bv = __shfl_sync(0xffffffffu, bv, 0);
            bi = __shfl_sync(0xffffffffu, bi, 0);
            if (bi == tid)      v0 = -INFINITY;
            if (bi == tid + 32) v1 = -INFINITY;
            tv[r] = bv; tix[r] = bi;
        }
        if (tid == 0) {
            float m = tv[0], wv[TK], D = 0.f;
#pragma unroll
            for (int r = 0; r < TK; r++) { wv[r] = expf(tv[r] - m); D += wv[r]; }
            D = fmaxf(D, 1.1920929e-7f);
#pragma unroll
            for (int r = 0; r < TK; r++) { g_topw[s][r] = wv[r] / D; g_topi[s][r] = tix[r]; }
        }
    }
}

// ---------------- priority ----------------
__global__ void priority_kernel(const int* __restrict__ capacity) {
    int e = blockIdx.x, lane = threadIdx.x;
    int cap = capacity[0];
    if (cap > CAPMAX) cap = CAPMAX;
    if (cap < 0) cap = 0;

    int offset = 0;
    for (int base = 0; base < S_TOK * TK; base += 32) {
        int p = base + lane;
        int k = p / S_TOK;
        int s = p - k * S_TOK;
        bool match = (g_topi[s][k] == e);
        unsigned mask = __ballot_sync(0xffffffffu, match);
        if (match) {
            int c = offset + __popc(mask & ((1u << lane) - 1u));
            if (c < cap) { g_slot[s][k] = c; g_etok[e][c] = s; }
            else         { g_slot[s][k] = -1; }
        }
        offset += __popc(mask);
    }
    if (lane == 0) g_ecount[e] = (offset < cap) ? offset : cap;
}

// ---------------- GEMM1 (fp16 mma m16n8k16) + SwiGLU ----------------
// 128 rows x 64 cols pair (g1+g2); 8 warps 2(M-interleave)x4(N).
__global__ __launch_bounds__(256, 2)
void gemm1_mma(const float* __restrict__ Wsh,
               const float* __restrict__ Wex) {
    int b = blockIdx.x;
    int M, x, y; const int* gather; const float* Wp; __half* Out;
    if (b < G1_EXP_BLKS) {
        int e   = b / 96;
        int rem = b - e * 96;
        y = rem / 48; x = rem - y * 48;
        M = g_ecount[e]; gather = g_etok[e];
        Wp = Wex + (size_t)e * I2 * HID; Out = &g_ex_gated[e][0][0];
    } else {
        int b2 = b - G1_EXP_BLKS;
        y = b2 / 48; x = b2 - y * 48;
        M = S_TOK; gather = nullptr; Wp = Wsh; Out = &g_sh_gated[0][0];
    }
    int m0 = y * BM;
    if (m0 >= M) return;
    int n0 = x * 64;
    int Mrem = M - m0; if (Mrem > BM) Mrem = BM;
    int ntiles = (Mrem + 15) >> 4;          // 16-row sub-tiles
    int npass64 = (ntiles * 16 + 63) >> 6;  // 64-row A loader passes

    uint32_t sb = smem_u32(dsm);
    int t = threadIdx.x, lane = t & 31, wid = t >> 5;
    int wm = wid >> 2, wn = wid & 3;
    int lq = lane >> 2, lr = lane & 3;

    // A loader: 16B (8 halves) per thread, 64 rows/pass, 2 passes
    int kseg = t & 3;           // half-offset kseg*8
    int r64  = t >> 2;          // 0..63
    const __half* ap[2]; int apred[2];
#pragma unroll
    for (int p = 0; p < 2; p++) {
        int m = m0 + p * 64 + r64;
        apred[p] = (p < npass64 && m < M);
        int mm = apred[p] ? (gather ? gather[m] : m) : 0;
        ap[p] = &g_xh[0][0] + (size_t)mm * HID + kseg * 8;
    }
    uint32_t aoff[2];
#pragma unroll
    for (int p = 0; p < 2; p++) aoff[p] = (uint32_t)((p * 64 + r64) * PRB + kseg * 16);

    // B loader: float4 per thread, 32 rows/pass, 4 passes (g1 rows 0..63, g2 rows 64..127)
    int kseg8 = t & 7;          // float-offset kseg8*4
    int r32   = t >> 3;         // 0..31
    const float* bp[4];
#pragma unroll
    for (int p = 0; p < 4; p++) {
        int row = p * 32 + r32;
        int wr = (row < 64) ? (n0 + row) : (n0 + row - 64 + I1);
        bp[p] = Wp + (size_t)wr * HID + kseg8 * 4;
    }
    uint32_t boff[4];
#pragma unroll
    for (int p = 0; p < 4; p++) boff[p] = (uint32_t)(A_BYTES + (p * 32 + r32) * PRB + kseg8 * 8);

    float acc1[4][2][4], acc2[4][2][4];
#pragma unroll
    for (int mt = 0; mt < 4; mt++)
#pragma unroll
        for (int nt = 0; nt < 2; nt++)
#pragma unroll
            for (int i = 0; i < 4; i++) { acc1[mt][nt][i] = 0.f; acc2[mt][nt][i] = 0.f; }

    float4 vbr[4];
    // prologue: chunk 0 -> buf 0
#pragma unroll
    for (int p = 0; p < 2; p++) cpa16(sb + aoff[p], ap[p], apred[p]);
    CP_COMMIT();
#pragma unroll
    for (int p = 0; p < 4; p++) vbr[p] = *(const float4*)(bp[p]);
#pragma unroll
    for (int p = 0; p < 4; p++) cvt_sts_h(sb + boff[p], vbr[p]);
    CP_WAIT0();
    __syncthreads();

#pragma unroll 1
    for (int kc = 0; kc < NC1; kc++) {
        int buf = kc & 1;
        if (kc + 1 < NC1) {
            int koh = (kc + 1) * BK;            // halves
            int kof = (kc + 1) * BK;            // floats
            uint32_t S2 = sb + (buf ^ 1) * STG;
#pragma unroll
            for (int p = 0; p < 2; p++) cpa16(S2 + aoff[p], ap[p] + koh, apred[p]);
            CP_COMMIT();
#pragma unroll
            for (int p = 0; p < 4; p++) vbr[p] = *(const float4*)(bp[p] + kof);
        }
        uint32_t Ab = sb + buf * STG;
        uint32_t Bb = Ab + A_BYTES;
#pragma unroll
        for (int ks = 0; ks < 2; ks++) {
            uint32_t kcol = (uint32_t)((ks * 8 + lr) * 4);
            uint32_t b1v[2][2], b2v[2][2];
#pragma unroll
            for (int nt = 0; nt < 2; nt++) {
                uint32_t base1 = Bb + (uint32_t)((wn * 16 + nt * 8 + lq) * PRB) + kcol;
                b1v[nt][0] = lds_u32(base1);
                b1v[nt][1] = lds_u32(base1 + 16);
                uint32_t base2 = base1 + 64 * PRB;
                b2v[nt][0] = lds_u32(base2);
                b2v[nt][1] = lds_u32(base2 + 16);
            }
#pragma unroll
            for (int mt = 0; mt < 4; mt++) {
                int ti = mt * 2 + wm;
                if (ti < ntiles) {
                    uint32_t a[4];
                    uint32_t base = Ab + (uint32_t)((ti * 16 + lq) * PRB) + kcol;
                    a[0] = lds_u32(base);
                    a[1] = lds_u32(base + 8 * PRB);
                    a[2] = lds_u32(base + 16);
                    a[3] = lds_u32(base + 8 * PRB + 16);
#pragma unroll
                    for (int nt = 0; nt < 2; nt++) {
                        MMA_F16(acc1[mt][nt], a, b1v[nt][0], b1v[nt][1]);
                        MMA_F16(acc2[mt][nt], a, b2v[nt][0], b2v[nt][1]);
                    }
                }
            }
        }
        if (kc + 1 < NC1) {
            uint32_t S2 = sb + (buf ^ 1) * STG;
#pragma unroll
            for (int p = 0; p < 4; p++) cvt_sts_h(S2 + boff[p], vbr[p]);
        }
        CP_WAIT0();
        __syncthreads();
    }

    // epilogue: fused SwiGLU -> fp16 output
#pragma unroll
    for (int mt = 0; mt < 4; mt++) {
        int ti = mt * 2 + wm;
        if (ti >= ntiles) continue;
        int rbase = m0 + ti * 16 + lq;
#pragma unroll
        for (int nt = 0; nt < 2; nt++) {
            int col = n0 + wn * 16 + nt * 8 + lr * 2;
#pragma unroll
            for (int half = 0; half < 2; half++) {
                int r = rbase + half * 8;
                if (r < M) {
                    float g1a = acc1[mt][nt][half * 2 + 0];
                    float g1b = acc1[mt][nt][half * 2 + 1];
                    float g2a = acc2[mt][nt][half * 2 + 0];
                    float g2b = acc2[mt][nt][half * 2 + 1];
                    float oa = g1a * (g2a / (1.f + expf(-g2a)));
                    float ob = g1b * (g2b / (1.f + expf(-g2b)));
                    *(uint32_t*)&Out[(size_t)r * I1 + col] = f2h2(oa, ob);
                }
            }
        }
    }
}

// ---------------- GEMM2 (fp16 mma m16n8k16): 128 x 128 ----------------
__global__ __launch_bounds__(256, 2)
void gemm2_mma(const float* __restrict__ Wsh,
               const float* __restrict__ Wex,
               float* __restrict__ dout) {
    int b = blockIdx.x;
    int M, x, y; const __half* G; const float* Wp; float* Out;
    if (b < G2_EXP_BLKS) {
        int e   = b / 12;
        int rem = b - e * 12;
        y = rem / 6; x = rem - y * 6;
        M = g_ecount[e]; G = &g_ex_gated[e][0][0];
        Wp = Wex + (size_t)e * HID * I1; Out = &g_ex_out[e][0][0];
    } else {
        int b2 = b - G2_EXP_BLKS;
        y = b2 / 6; x = b2 - y * 6;
        M = S_TOK; G = &g_sh_gated[0][0]; Wp = Wsh; Out = dout;
    }
    int m0 = y * BM;
    if (m0 >= M) return;
    int n0 = x * 128;
    int Mrem = M - m0; if (Mrem > BM) Mrem = BM;
    int ntiles = (Mrem + 15) >> 4;
    int npass64 = (ntiles * 16 + 63) >> 6;

    uint32_t sb = smem_u32(dsm);
    int t = threadIdx.x, lane = t & 31, wid = t >> 5;
    int wm = wid >> 2, wn = wid & 3;
    int lq = lane >> 2, lr = lane & 3;

    int kseg = t & 3;
    int r64  = t >> 2;
    const __half* ap[2]; int apred[2];
#pragma unroll
    for (int p = 0; p < 2; p++) {
        int m = m0 + p * 64 + r64;
        apred[p] = (p < npass64 && m < M);
        int mm = apred[p] ? m : 0;
        ap[p] = G + (size_t)mm * I1 + kseg * 8;
    }
    uint32_t aoff[2];
#pragma unroll
    for (int p = 0; p < 2; p++) aoff[p] = (uint32_t)((p * 64 + r64) * PRB + kseg * 16);

    int kseg8 = t & 7;
    int r32   = t >> 3;
    const float* bp[4];
#pragma unroll
    for (int p = 0; p < 4; p++)
        bp[p] = Wp + (size_t)(n0 + p * 32 + r32) * I1 + kseg8 * 4;
    uint32_t boff[4];
#pragma unroll
    for (int p = 0; p < 4; p++) boff[p] = (uint32_t)(A_BYTES + (p * 32 + r32) * PRB + kseg8 * 8);

    float acc[4][4][4];
#pragma unroll
    for (int mt = 0; mt < 4; mt++)
#pragma unroll
        for (int nt = 0; nt < 4; nt++)
#pragma unroll
            for (int i = 0; i < 4; i++) acc[mt][nt][i] = 0.f;

    float4 vbr[4];
#pragma unroll
    for (int p = 0; p < 2; p++) cpa16(sb + aoff[p], ap[p], apred[p]);
    CP_COMMIT();
#pragma unroll
    for (int p = 0; p < 4; p++) vbr[p] = *(const float4*)(bp[p]);
#pragma unroll
    for (int p = 0; p < 4; p++) cvt_sts_h(sb + boff[p], vbr[p]);
    CP_WAIT0();
    __syncthreads();

#pragma unroll 1
    for (int kc = 0; kc < NC2; kc++) {
        int buf = kc & 1;
        if (kc + 1 < NC2) {
            int koh = (kc + 1) * BK;
            int kof = (kc + 1) * BK;
            uint32_t S2 = sb + (buf ^ 1) * STG;
#pragma unroll
            for (int p = 0; p < 2; p++) cpa16(S2 + aoff[p], ap[p] + koh, apred[p]);
            CP_COMMIT();
#pragma unroll
            for (int p = 0; p < 4; p++) vbr[p] = *(const float4*)(bp[p] + kof);
        }
        uint32_t Ab = sb + buf * STG;
        uint32_t Bb = Ab + A_BYTES;
#pragma unroll
        for (int ks = 0; ks < 2; ks++) {
            uint32_t kcol = (uint32_t)((ks * 8 + lr) * 4);
            uint32_t bv[4][2];
#pragma unroll
            for (int nt = 0; nt < 4; nt++) {
                uint32_t base = Bb + (uint32_t)((wn * 32 + nt * 8 + lq) * PRB) + kcol;
                bv[nt][0] = lds_u32(base);
                bv[nt][1] = lds_u32(base + 16);
            }
#pragma unroll
            for (int mt = 0; mt < 4; mt++) {
                int ti = mt * 2 + wm;
                if (ti < ntiles) {
                    uint32_t a[4];
                    uint32_t base = Ab + (uint32_t)((ti * 16 + lq) * PRB) + kcol;
                    a[0] = lds_u32(base);
                    a[1] = lds_u32(base + 8 * PRB);
                    a[2] = lds_u32(base + 16);
                    a[3] = lds_u32(base + 8 * PRB + 16);
#pragma unroll
                    for (int nt = 0; nt < 4; nt++)
                        MMA_F16(acc[mt][nt], a, bv[nt][0], bv[nt][1]);
                }
            }
        }
        if (kc + 1 < NC2) {
            uint32_t S2 = sb + (buf ^ 1) * STG;
#pragma unroll
            for (int p = 0; p < 4; p++) cvt_sts_h(S2 + boff[p], vbr[p]);
        }
        CP_WAIT0();
        __syncthreads();
    }

#pragma unroll
    for (int mt = 0; mt < 4; mt++) {
        int ti = mt * 2 + wm;
        if (ti >= ntiles) continue;
        int rbase = m0 + ti * 16 + lq;
#pragma unroll
        for (int nt = 0; nt < 4; nt++) {
            int col = n0 + wn * 32 + nt * 8 + lr * 2;
#pragma unroll
            for (int half = 0; half < 2; half++) {
                int r = rbase + half * 8;
                if (r < M) {
                    float2 o;
                    o.x = acc[mt][nt][half * 2 + 0];
                    o.y = acc[mt][nt][half * 2 + 1];
                    *(float2*)&Out[(size_t)r * HID + col] = o;
                }
            }
        }
    }
}

// ---------------- combine ----------------
__global__ void combine_kernel(float* __restrict__ out) {
    int s = blockIdx.x, tid = threadIdx.x;
    __shared__ int ke[TK], kc_[TK];
    __shared__ float kw[TK];
    if (tid < TK) { ke[tid] = g_topi[s][tid]; kc_[tid] = g_slot[s][tid]; kw[tid] = g_topw[s][tid]; }
    __syncthreads();
    for (int h = tid; h < HID; h += 256) {
        float acc = out[(size_t)s * HID + h];
#pragma unroll
        for (int k = 0; k < TK; k++) {
            int c = kc_[k];
            if (c >= 0) acc += kw[k] * g_ex_out[ke[k]][c][h];
        }
        out[(size_t)s * HID + h] = acc;
    }
}

// ---------------------------------------------------------------------------
extern "C" void kernel_launch(void* const* d_in, const int* in_sizes, int n_in,
                              void* d_out, int out_size) {
    const float* x      = (const float*)d_in[0];
    const float* w_gu   = (const float*)d_in[1];
    const float* w_down = (const float*)d_in[2];
    const float* wg     = (const float*)d_in[3];
    const float* w1     = (const float*)d_in[4];
    const float* w2     = (const float*)d_in[5];
    const int*   cap    = (const int*)d_in[6];
    float* out = (float*)d_out;

    cudaFuncSetAttribute(gemm1_mma, cudaFuncAttributeMaxDynamicSharedMemorySize, SMEM_BYTES);
    cudaFuncSetAttribute(gemm2_mma, cudaFuncAttributeMaxDynamicSharedMemorySize, SMEM_BYTES);

    gating_kernel<<<S_TOK, 256>>>(x, wg);
    round_x_kernel<<<S_TOK * HID / 1024, 256>>>(x);
    priority_kernel<<<NE, 32>>>(cap);

    gemm1_mma<<<G1_EXP_BLKS + G1_SH_BLKS, 256, SMEM_BYTES>>>(w_gu, w1);
    gemm2_mma<<<G2_EXP_BLKS + G2_SH_BLKS, 256, SMEM_BYTES>>>(w_down, w2, out);

    combine_kernel<<<S_TOK, 256>>>(out);
}